// round 14
// baseline (speedup 1.0000x reference)
#include <cuda_runtime.h>
#include <cuda_fp16.h>
#include <cstdint>
#include <cstddef>

#define NNODES 16384
#define FDIM   768
#define DEG    4

// ---------------- scratch (device globals; no allocation allowed) ----------
__device__ float  g_P1[FDIM * 8];
__device__ float  g_P2[FDIM * 2];
__device__ float  g_zerob[FDIM];                      // zero bias (static-zeroed)
__device__ __half g_W1ph[(size_t)4 * FDIM * FDIM];    // [3072,768] B GEMM1 (x0.25, fp16)
__device__ __half g_W2rh[(size_t)FDIM * FDIM];        // [768,768]  B GEMM2 (fp16)
__device__ float  g_e1[(size_t)NNODES * 8];
__device__ float  g_e2[(size_t)NNODES * 2];
__device__ __half g_xh[(size_t)NNODES * FDIM];        // x in fp16 (emitted by compute_e8)
__device__ __half g_agg1h[(size_t)NNODES * 4 * FDIM]; // [N,3072] A GEMM1 (fp16)
__device__ __half g_preh[(size_t)NNODES * FDIM];      // GEMM output (fp16)
__device__ __half g_x1h[(size_t)NNODES * FDIM];       // layer-1 output (fp16)
__device__ int    g_is64;

// ---------------- helpers ---------------------------------------------------
__device__ __forceinline__ uint32_t smem_u32(const void* p) {
    uint32_t a;
    asm("{ .reg .u64 t; cvta.to.shared.u64 t, %1; cvt.u32.u64 %0, t; }" : "=r"(a) : "l"(p));
    return a;
}

__device__ __forceinline__ void cp16(uint32_t s, const void* g) {
    asm volatile("cp.async.cg.shared.global [%0], [%1], 16;" :: "r"(s), "l"(g));
}

__device__ __forceinline__ void ldsm_x4(uint32_t* r, uint32_t addr) {
    asm volatile("ldmatrix.sync.aligned.m8n8.x4.shared.b16 {%0,%1,%2,%3}, [%4];"
                 : "=r"(r[0]), "=r"(r[1]), "=r"(r[2]), "=r"(r[3]) : "r"(addr));
}

__device__ __forceinline__ void ldsm_x4_t(uint32_t* r, uint32_t addr) {
    asm volatile("ldmatrix.sync.aligned.m8n8.x4.trans.shared.b16 {%0,%1,%2,%3}, [%4];"
                 : "=r"(r[0]), "=r"(r[1]), "=r"(r[2]), "=r"(r[3]) : "r"(addr));
}

__device__ __forceinline__ void mma_f16(float* d, const uint32_t* a, const uint32_t* b) {
    asm volatile(
        "mma.sync.aligned.m16n8k16.row.col.f32.f16.f16.f32 "
        "{%0,%1,%2,%3}, {%4,%5,%6,%7}, {%8,%9}, {%0,%1,%2,%3};"
        : "+f"(d[0]), "+f"(d[1]), "+f"(d[2]), "+f"(d[3])
        : "r"(a[0]), "r"(a[1]), "r"(a[2]), "r"(a[3]), "r"(b[0]), "r"(b[1]));
}

__device__ __forceinline__ float block_reduce_384(float v, float* red) {
#pragma unroll
    for (int o = 16; o; o >>= 1) v += __shfl_down_sync(0xffffffffu, v, o);
    if ((threadIdx.x & 31) == 0) red[threadIdx.x >> 5] = v;
    __syncthreads();
    float r = 0.f;
    if (threadIdx.x < 12) r = red[threadIdx.x];
    if (threadIdx.x < 32) {
#pragma unroll
        for (int o = 8; o; o >>= 1) r += __shfl_down_sync(0xffffffffu, r, o);
    }
    return r;
}

// ---------------- edge dtype probe (standalone) -------------------------------
__global__ void probe(const unsigned long long* __restrict__ edge) {
    __shared__ int bad;
    if (threadIdx.x == 0) bad = 0;
    __syncthreads();
    for (int i = threadIdx.x; i < 1024; i += 256)
        if (edge[i] > 0xFFFFFFFFull) bad = 1;
    __syncthreads();
    if (threadIdx.x == 0) g_is64 = bad ? 0 : 1;
}

// ---------------- prepP: P vectors (1 block per k-row) -----------------------
__global__ void __launch_bounds__(256) prepP(
    const float* __restrict__ W1, const float* __restrict__ a1s, const float* __restrict__ a1d,
    const float* __restrict__ W2, const float* __restrict__ a2s, const float* __restrict__ a2d)
{
    int k = blockIdx.x;
    int wid = threadIdx.x >> 5, lane = threadIdx.x & 31;
    {
        int h = wid & 3;
        const float* w = W1 + (size_t)k * (4 * FDIM) + h * FDIM;
        const float* a = (wid < 4 ? a1s : a1d) + h * FDIM;
        float s = 0.f;
        for (int i = lane; i < FDIM; i += 32) s += w[i] * a[i];
#pragma unroll
        for (int o = 16; o; o >>= 1) s += __shfl_down_sync(0xffffffffu, s, o);
        if (lane == 0) g_P1[k * 8 + wid] = s;
    }
    if (wid < 2) {
        const float* w = W2 + (size_t)k * FDIM;
        const float* a = (wid == 0) ? a2s : a2d;
        float s = 0.f;
        for (int i = lane; i < FDIM; i += 32) s += w[i] * a[i];
#pragma unroll
        for (int o = 16; o; o >>= 1) s += __shfl_down_sync(0xffffffffu, s, o);
        if (lane == 0) g_P2[k * 2 + wid] = s;
    }
}

// ---------------- prepW: W1 repack (x0.25) + W2 convert to fp16 --------------
#define PREP_WELEM ((size_t)5 * FDIM * FDIM)
#define PREP_WBLK ((int)((PREP_WELEM + 255) / 256))

__global__ void __launch_bounds__(256) prepW(const float* __restrict__ W1,
                                             const float* __restrict__ W2)
{
    const size_t S1 = (size_t)4 * FDIM * FDIM;
    size_t idx = (size_t)blockIdx.x * 256 + threadIdx.x;
    if (idx < S1) {
        int j = (int)(idx % FDIM);
        int r = (int)(idx / FDIM);     // h*768 + k
        int h = r / FDIM, k = r % FDIM;
        g_W1ph[idx] = __float2half(0.25f * W1[(size_t)k * (4 * FDIM) + h * FDIM + j]);
    } else if (idx < PREP_WELEM) {
        size_t i2 = idx - S1;
        g_W2rh[i2] = __float2half(W2[i2]);
    }
}

// ---------------- e1 = x @ P1, also emit x as fp16 (2 nodes/warp) ------------
__global__ void __launch_bounds__(256) compute_e8(
    const float* __restrict__ x, const float* __restrict__ P,
    float* __restrict__ e, __half* __restrict__ xh)
{
    __shared__ __align__(16) float sP[8 * FDIM];   // transposed [j][k]
    for (int i = threadIdx.x; i < 8 * FDIM; i += 256) {
        int j = i / FDIM, k = i % FDIM;
        sP[j * FDIM + k] = P[k * 8 + j];
    }
    __syncthreads();
    const float4* sP4 = (const float4*)sP;         // [8][192]
    int warp = threadIdx.x >> 5, lane = threadIdx.x & 31;
    int n0 = (blockIdx.x * 8 + warp) * 2;          // grid = 1024 -> 2 nodes/warp
    const float4* xr0 = (const float4*)(x + (size_t)n0 * FDIM);
    const float4* xr1 = (const float4*)(x + (size_t)(n0 + 1) * FDIM);
    uint2* xw0 = (uint2*)(xh + (size_t)n0 * FDIM);
    uint2* xw1 = (uint2*)(xh + (size_t)(n0 + 1) * FDIM);
    float acc0[8], acc1[8];
#pragma unroll
    for (int j = 0; j < 8; j++) { acc0[j] = 0.f; acc1[j] = 0.f; }
#pragma unroll
    for (int it = 0; it < 6; it++) {
        float4 v0 = xr0[lane + it * 32];
        float4 v1 = xr1[lane + it * 32];
        {
            __half2 h0 = __floats2half2_rn(v0.x, v0.y);
            __half2 h1 = __floats2half2_rn(v0.z, v0.w);
            uint2 hw; hw.x = *(uint32_t*)&h0; hw.y = *(uint32_t*)&h1;
            xw0[lane + it * 32] = hw;
        }
        {
            __half2 h0 = __floats2half2_rn(v1.x, v1.y);
            __half2 h1 = __floats2half2_rn(v1.z, v1.w);
            uint2 hw; hw.x = *(uint32_t*)&h0; hw.y = *(uint32_t*)&h1;
            xw1[lane + it * 32] = hw;
        }
#pragma unroll
        for (int j = 0; j < 8; j++) {
            float4 p = sP4[j * 192 + lane + it * 32];   // one LDS feeds 2 nodes
            acc0[j] += v0.x * p.x + v0.y * p.y + v0.z * p.z + v0.w * p.w;
            acc1[j] += v1.x * p.x + v1.y * p.y + v1.z * p.z + v1.w * p.w;
        }
    }
#pragma unroll
    for (int j = 0; j < 8; j++) {
        float s0 = acc0[j], s1 = acc1[j];
#pragma unroll
        for (int o = 16; o; o >>= 1) {
            s0 += __shfl_down_sync(0xffffffffu, s0, o);
            s1 += __shfl_down_sync(0xffffffffu, s1, o);
        }
        if (lane == 0) {
            e[(size_t)n0 * 8 + j] = s0;
            e[(size_t)(n0 + 1) * 8 + j] = s1;
        }
    }
}

// ---------------- layer-1 softmax + weighted gather: 4 nodes/block -----------
__global__ void __launch_bounds__(384) aggregate1(
    const __half* __restrict__ x, const float* __restrict__ e,
    const void* __restrict__ edge, __half* __restrict__ agg)
{
    int n0 = blockIdx.x * 4;
    __shared__ int   s_src[4][5];
    __shared__ float s_alpha[4][4][5];
    int tid = threadIdx.x;
    if (tid < 20) {
        int node = tid / 5, k = tid % 5;
        int n = n0 + node;
        int sv = n;
        if (k < 4) {
            sv = g_is64 ? (int)((const long long*)edge)[(size_t)DEG * n + k]
                        : ((const int*)edge)[DEG * n + k];
        }
        s_src[node][k] = sv;
    }
    __syncthreads();
    if (tid < 16) {
        int node = tid >> 2, h = tid & 3;
        int n = n0 + node;
        float ed = e[(size_t)n * 8 + 4 + h];
        float l[5];
#pragma unroll
        for (int k = 0; k < 5; k++) {
            float v = e[(size_t)s_src[node][k] * 8 + h] + ed;
            l[k] = v >= 0.f ? v : 0.2f * v;
        }
        float m = l[0];
#pragma unroll
        for (int k = 1; k < 5; k++) m = fmaxf(m, l[k]);
        float s = 0.f;
#pragma unroll
        for (int k = 0; k < 5; k++) { l[k] = expf(l[k] - m); s += l[k]; }
        float inv = 1.f / (s + 1e-16f);
#pragma unroll
        for (int k = 0; k < 5; k++) s_alpha[node][h][k] = l[k] * inv;
    }
    __syncthreads();
    int d2 = tid;  // 384 threads x 2 dims = 768
#pragma unroll
    for (int node = 0; node < 4; node++) {
        int n = n0 + node;
        float2 xv[5];
#pragma unroll
        for (int k = 0; k < 5; k++)
            xv[k] = __half22float2(
                ((const __half2*)(x + (size_t)s_src[node][k] * FDIM))[d2]);
#pragma unroll
        for (int h = 0; h < 4; h++) {
            float ax = 0.f, ay = 0.f;
#pragma unroll
            for (int k = 0; k < 5; k++) {
                float al = s_alpha[node][h][k];
                ax += al * xv[k].x;
                ay += al * xv[k].y;
            }
            ((__half2*)(agg + ((size_t)n * 4 + h) * FDIM))[d2] =
                __floats2half2_rn(ax, ay);
        }
    }
}

// ---------------- fp16 mma.sync persistent GEMM (BK=32, 4-stage) -------------
#define BM 128
#define BN 128
#define BK 32
#define ASTRH 40
#define BSTRH 136
#define A_STG (BM * ASTRH)
#define B_STG (BK * BSTRH)
#define NSTAGE 4
#define GEMM_SMEM (NSTAGE * (A_STG + B_STG) * 2)

__global__ void __launch_bounds__(256, 2) gemm_fp16(
    const __half* __restrict__ A, const __half* __restrict__ B,
    const float* __restrict__ bias, __half* __restrict__ C,
    int Nn, int K, int ntiles, int T)
{
    extern __shared__ __half hsm[];
    uint32_t asb = smem_u32(hsm);
    uint32_t bsb = asb + NSTAGE * A_STG * 2;

    int tid = threadIdx.x;
    int lane = tid & 31, wid = tid >> 5;
    int warpM = wid & 1, warpN = wid >> 1;
    int g = lane >> 2, tg = lane & 3;
    int KT = K / BK;

    int ar = tid >> 2, ac8 = (tid & 3) * 8;
    int br = tid >> 4, bc8 = (tid & 15) * 8;

    auto load_stage = [&](int s, int k0, int bm, int bn) {
#pragma unroll
        for (int t = 0; t < 2; t++) {
            int r = ar + t * 64;
            cp16(asb + (uint32_t)(s * A_STG + r * ASTRH + ac8) * 2,
                 A + (size_t)(bm + r) * K + k0 + ac8);
        }
#pragma unroll
        for (int t = 0; t < 2; t++) {
            int r = br + t * 16;
            cp16(bsb + (uint32_t)(s * B_STG + r * BSTRH + bc8) * 2,
                 B + (size_t)(k0 + r) * Nn + bn + bc8);
        }
        asm volatile("cp.async.commit_group;");
    };

    uint32_t a_off = (uint32_t)((warpM * 64 + (lane & 15)) * ASTRH + (lane >> 4) * 8);
    uint32_t b_off = (uint32_t)((lane & 15) * BSTRH + warpN * 32 + (lane >> 4) * 8);

    int t0 = blockIdx.x;
    if (t0 >= T) return;
    {
        int bm = (t0 / ntiles) * BM, bn = (t0 % ntiles) * BN;
        load_stage(0, 0, bm, bn);
        load_stage(1, BK, bm, bn);
        load_stage(2, 2 * BK, bm, bn);
    }

    for (int t = t0; t < T; t += gridDim.x) {
        int bm = (t / ntiles) * BM, bn = (t % ntiles) * BN;
        int tn = t + gridDim.x; if (tn >= T) tn = t;
        int bm2 = (tn / ntiles) * BM, bn2 = (tn % ntiles) * BN;

        float acc[4][4][4];
#pragma unroll
        for (int i = 0; i < 4; i++)
#pragma unroll
            for (int j = 0; j < 4; j++)
#pragma unroll
                for (int r = 0; r < 4; r++) acc[i][j][r] = 0.f;

        for (int kt = 0; kt < KT; kt++) {
            asm volatile("cp.async.wait_group 2;");
            __syncthreads();

            int pf = kt + NSTAGE - 1;
            if (pf < KT) load_stage(pf & 3, pf * BK, bm, bn);
            else         load_stage(pf & 3, (pf - KT) * BK, bm2, bn2);

            int buf = kt & 3;
            uint32_t a_base = asb + (buf * A_STG + a_off) * 2;
            uint32_t b_base = bsb + (buf * B_STG + b_off) * 2;
#pragma unroll
            for (int ks = 0; ks < 2; ks++) {
                uint32_t af[4][4], bf[2][4];
#pragma unroll
                for (int mt = 0; mt < 4; mt++)
                    ldsm_x4(af[mt], a_base + (uint32_t)(mt * 16 * ASTRH + ks * 16) * 2);
#pragma unroll
                for (int np = 0; np < 2; np++)
                    ldsm_x4_t(bf[np], b_base + (uint32_t)(ks * 16 * BSTRH + np * 16) * 2);
#pragma unroll
                for (int mt = 0; mt < 4; mt++)
#pragma unroll
                    for (int np = 0; np < 2; np++) {
                        mma_f16(acc[mt][np * 2 + 0], af[mt], &bf[np][0]);
                        mma_f16(acc[mt][np * 2 + 1], af[mt], &bf[np][2]);
                    }
            }
        }

#pragma unroll
        for (int mt = 0; mt < 4; mt++) {
            int row = bm + warpM * 64 + mt * 16 + g;
#pragma unroll
            for (int nt = 0; nt < 4; nt++) {
                int col = bn + warpN * 32 + nt * 8 + tg * 2;
                float b0 = bias[col], b1 = bias[col + 1];
                *(__half2*)(C + (size_t)row * Nn + col) =
                    __floats2half2_rn(acc[mt][nt][0] + b0, acc[mt][nt][1] + b1);
                *(__half2*)(C + (size_t)(row + 8) * Nn + col) =
                    __floats2half2_rn(acc[mt][nt][2] + b0, acc[mt][nt][3] + b1);
            }
        }
    }
    asm volatile("cp.async.wait_group 0;");
}

// ---------------- elu + LN + fused e2 logits (384 thr, half2) ----------------
__global__ void __launch_bounds__(384) elu_ln_e2(
    const __half* __restrict__ in, const float* __restrict__ gamma,
    const float* __restrict__ beta, const float* __restrict__ P2,
    __half* __restrict__ out, float* __restrict__ e2)
{
    __shared__ float red[12];
    __shared__ float s_mu, s_w;
    int n = blockIdx.x;
    int tid = threadIdx.x;
    int d2 = tid;
    float2 v = __half22float2(((const __half2*)(in + (size_t)n * FDIM))[d2]);
    float yx = v.x > 0.f ? v.x : expm1f(v.x);
    float yy = v.y > 0.f ? v.y : expm1f(v.y);
    float tot = block_reduce_384(yx + yy, red);
    if (tid == 0) s_mu = tot * (1.f / FDIM);
    __syncthreads();
    float mu = s_mu;
    float dx = yx - mu, dy = yy - mu;
    float totq = block_reduce_384(dx * dx + dy * dy, red);
    if (tid == 0) s_w = rsqrtf(totq * (1.f / FDIM) + 1e-5f);
    __syncthreads();
    float w = s_w;
    float ox = dx * w * gamma[d2 * 2 + 0] + beta[d2 * 2 + 0];
    float oy = dy * w * gamma[d2 * 2 + 1] + beta[d2 * 2 + 1];
    ((__half2*)(out + (size_t)n * FDIM))[d2] = __floats2half2_rn(ox, oy);
    // fused e2 = x1 . P2
    float s0 = ox * P2[d2 * 4 + 0] + oy * P2[d2 * 4 + 2];
    float s1 = ox * P2[d2 * 4 + 1] + oy * P2[d2 * 4 + 3];
    __syncthreads();
    float t0 = block_reduce_384(s0, red);
    if (tid == 0) e2[(size_t)n * 2 + 0] = t0;
    __syncthreads();
    float t1 = block_reduce_384(s1, red);
    if (tid == 0) e2[(size_t)n * 2 + 1] = t1;
}

// ---------------- fused layer-2 epilogue: gather(pre2) + bias + elu + LN + clip
__global__ void __launch_bounds__(384) agg2_ln_f(
    const __half* __restrict__ pre, const float* __restrict__ e2,
    const void* __restrict__ edge, const float* __restrict__ b2,
    const float* __restrict__ gamma, const float* __restrict__ beta,
    float* __restrict__ out)
{
    __shared__ int   s_src[5];
    __shared__ float s_alpha[5];
    __shared__ float red[12];
    __shared__ float s_mu, s_w;
    int n = blockIdx.x;
    int tid = threadIdx.x;
    if (tid < 5) {
        int sv = n;
        if (tid < 4) {
            sv = g_is64 ? (int)((const long long*)edge)[(size_t)DEG * n + tid]
                        : ((const int*)edge)[DEG * n + tid];
        }
        s_src[tid] = sv;
    }
    __syncthreads();
    if (tid == 0) {
        float ed = e2[(size_t)n * 2 + 1];
        float l[5];
#pragma unroll
        for (int k = 0; k < 5; k++) {
            float v = e2[(size_t)s_src[k] * 2 + 0] + ed;
            l[k] = v >= 0.f ? v : 0.2f * v;
        }
        float m = l[0];
#pragma unroll
        for (int k = 1; k < 5; k++) m = fmaxf(m, l[k]);
        float s = 0.f;
#pragma unroll
        for (int k = 0; k < 5; k++) { l[k] = expf(l[k] - m); s += l[k]; }
        float inv = 1.f / (s + 1e-16f);
#pragma unroll
        for (int k = 0; k < 5; k++) s_alpha[k] = l[k] * inv;
    }
    __syncthreads();
    int d2 = tid;
    float ax = 0.f, ay = 0.f;
#pragma unroll
    for (int k = 0; k < 5; k++) {
        float2 v = __half22float2(((const __half2*)(pre + (size_t)s_src[k] * FDIM))[d2]);
        float al = s_alpha[k];
        ax += al * v.x;
        ay += al * v.y;
    }
    ax += b2[d2 * 2 + 0];
    ay += b2[d2 * 2 + 1];
    float yx = ax > 0.f ? ax : expm1f(ax);
    float yy = ay > 0.f ? ay : expm1f(ay);
    float tot = block_reduce_384(yx + yy, red);
    if (tid == 0) s_mu = tot * (1.f / FDIM);
    __syncthreads();
    float mu = s_mu;
    float dx = yx - mu, dy = yy - mu;
    float totq = block_reduce_384(dx * dx + dy * dy, red);
    if (tid == 0) s_w = rsqrtf(totq * (1.f / FDIM) + 1e-5f);
    __syncthreads();
    float w = s_w;
    float ox = dx * w * gamma[d2 * 2 + 0] + beta[d2 * 2 + 0];
    float oy = dy * w * gamma[d2 * 2 + 1] + beta[d2 * 2 + 1];
    ox = fminf(fmaxf(ox, -10000.f), 10000.f);
    oy = fminf(fmaxf(oy, -10000.f), 10000.f);
    ((float2*)(out + (size_t)n * FDIM))[d2] = make_float2(ox, oy);
}

// ---------------- launch ------------------------------------------------------
extern "C" void kernel_launch(void* const* d_in, const int* in_sizes, int n_in,
                              void* d_out, int out_size)
{
    const float* x   = (const float*)d_in[0];
    const void*  ei  = d_in[1];
    const float* W1  = (const float*)d_in[2];
    const float* a1s = (const float*)d_in[3];
    const float* a1d = (const float*)d_in[4];
    const float* b1  = (const float*)d_in[5];
    const float* W2  = (const float*)d_in[6];
    const float* a2s = (const float*)d_in[7];
    const float* a2d = (const float*)d_in[8];
    const float* b2  = (const float*)d_in[9];
    const float* gm  = (const float*)d_in[10];
    const float* bt  = (const float*)d_in[11];
    float* out = (float*)d_out;

    float *p1, *p2, *e1, *e2, *zb;
    __half *w1ph, *w2rh, *xh, *agg1h, *preh, *x1h;
    cudaGetSymbolAddress((void**)&p1,    g_P1);
    cudaGetSymbolAddress((void**)&p2,    g_P2);
    cudaGetSymbolAddress((void**)&zb,    g_zerob);
    cudaGetSymbolAddress((void**)&w1ph,  g_W1ph);
    cudaGetSymbolAddress((void**)&w2rh,  g_W2rh);
    cudaGetSymbolAddress((void**)&e1,    g_e1);
    cudaGetSymbolAddress((void**)&e2,    g_e2);
    cudaGetSymbolAddress((void**)&xh,    g_xh);
    cudaGetSymbolAddress((void**)&agg1h, g_agg1h);
    cudaGetSymbolAddress((void**)&preh,  g_preh);
    cudaGetSymbolAddress((void**)&x1h,   g_x1h);

    cudaFuncSetAttribute(gemm_fp16, cudaFuncAttributeMaxDynamicSharedMemorySize, GEMM_SMEM);
    cudaFuncSetAttribute(gemm_fp16, cudaFuncAttributePreferredSharedMemoryCarveout, 100);

    const int T = (NNODES / BM) * (FDIM / BN);   // 768 tiles

    probe<<<1, 256>>>((const unsigned long long*)ei);                         // 1
    prepP<<<FDIM, 256>>>(W1, a1s, a1d, W2, a2s, a2d);                         // 2
    prepW<<<PREP_WBLK, 256>>>(W1, W2);                                        // 3

    // layer 1 (aggregate-then-project; head-mean folded into W1p)
    compute_e8<<<1024, 256>>>(x, p1, e1, xh);                                 // 4 (ncu)
    aggregate1<<<NNODES / 4, 384>>>(xh, e1, ei, agg1h);                       // 5
    gemm_fp16<<<296, 256, GEMM_SMEM>>>(agg1h, w1ph, b1, preh,                 // 6
                                       FDIM, 4 * FDIM, FDIM / BN, T);
    elu_ln_e2<<<NNODES, 384>>>(preh, gm, bt, p2, x1h, e2);                    // 7

    // layer 2 (project-then-aggregate; bias folded into fused epilogue)
    gemm_fp16<<<296, 256, GEMM_SMEM>>>(x1h, w2rh, zb, preh,                   // 8
                                       FDIM, FDIM, FDIM / BN, T);
    agg2_ln_f<<<NNODES, 384>>>(preh, e2, ei, b2, gm, bt, out);                // 9
}

// round 15
// speedup vs baseline: 1.0271x; 1.0271x over previous
#include <cuda_runtime.h>
#include <cuda_fp16.h>
#include <cstdint>
#include <cstddef>

#define NNODES 16384
#define FDIM   768
#define DEG    4

// ---------------- scratch (device globals; no allocation allowed) ----------
__device__ float  g_P1[FDIM * 8];
__device__ float  g_P2[FDIM * 2];
__device__ float  g_zerob[FDIM];                      // zero bias (static-zeroed)
__device__ __half g_W1ph[(size_t)4 * FDIM * FDIM];    // [3072,768] B GEMM1 (x0.25, fp16)
__device__ __half g_W2rh[(size_t)FDIM * FDIM];        // [768,768]  B GEMM2 (fp16)
__device__ float  g_e1[(size_t)NNODES * 8];
__device__ float  g_e2[(size_t)NNODES * 2];
__device__ __half g_xh[(size_t)NNODES * FDIM];        // x in fp16 (emitted by compute_e8)
__device__ __half g_agg1h[(size_t)NNODES * 4 * FDIM]; // [N,3072] A GEMM1 (fp16)
__device__ __half g_preh[(size_t)NNODES * FDIM];      // GEMM output (fp16)
__device__ __half g_x1h[(size_t)NNODES * FDIM];       // layer-1 output (fp16)
__device__ int    g_is64;

// ---------------- helpers ---------------------------------------------------
__device__ __forceinline__ uint32_t smem_u32(const void* p) {
    uint32_t a;
    asm("{ .reg .u64 t; cvta.to.shared.u64 t, %1; cvt.u32.u64 %0, t; }" : "=r"(a) : "l"(p));
    return a;
}

__device__ __forceinline__ void cp16(uint32_t s, const void* g) {
    asm volatile("cp.async.cg.shared.global [%0], [%1], 16;" :: "r"(s), "l"(g));
}

__device__ __forceinline__ void ldsm_x4(uint32_t* r, uint32_t addr) {
    asm volatile("ldmatrix.sync.aligned.m8n8.x4.shared.b16 {%0,%1,%2,%3}, [%4];"
                 : "=r"(r[0]), "=r"(r[1]), "=r"(r[2]), "=r"(r[3]) : "r"(addr));
}

__device__ __forceinline__ void ldsm_x4_t(uint32_t* r, uint32_t addr) {
    asm volatile("ldmatrix.sync.aligned.m8n8.x4.trans.shared.b16 {%0,%1,%2,%3}, [%4];"
                 : "=r"(r[0]), "=r"(r[1]), "=r"(r[2]), "=r"(r[3]) : "r"(addr));
}

__device__ __forceinline__ void mma_f16(float* d, const uint32_t* a, const uint32_t* b) {
    asm volatile(
        "mma.sync.aligned.m16n8k16.row.col.f32.f16.f16.f32 "
        "{%0,%1,%2,%3}, {%4,%5,%6,%7}, {%8,%9}, {%0,%1,%2,%3};"
        : "+f"(d[0]), "+f"(d[1]), "+f"(d[2]), "+f"(d[3])
        : "r"(a[0]), "r"(a[1]), "r"(a[2]), "r"(a[3]), "r"(b[0]), "r"(b[1]));
}

__device__ __forceinline__ float block_reduce_256(float v, float* red) {
#pragma unroll
    for (int o = 16; o; o >>= 1) v += __shfl_down_sync(0xffffffffu, v, o);
    if ((threadIdx.x & 31) == 0) red[threadIdx.x >> 5] = v;
    __syncthreads();
    float r = 0.f;
    if (threadIdx.x < 8) r = red[threadIdx.x];
    if (threadIdx.x < 32) {
#pragma unroll
        for (int o = 4; o; o >>= 1) r += __shfl_down_sync(0xffu, r, o);
    }
    return r;
}

__device__ __forceinline__ float block_reduce_384(float v, float* red) {
#pragma unroll
    for (int o = 16; o; o >>= 1) v += __shfl_down_sync(0xffffffffu, v, o);
    if ((threadIdx.x & 31) == 0) red[threadIdx.x >> 5] = v;
    __syncthreads();
    float r = 0.f;
    if (threadIdx.x < 12) r = red[threadIdx.x];
    if (threadIdx.x < 32) {
#pragma unroll
        for (int o = 8; o; o >>= 1) r += __shfl_down_sync(0xffffffffu, r, o);
    }
    return r;
}

// ---------------- edge dtype probe (standalone) -------------------------------
__global__ void probe(const unsigned long long* __restrict__ edge) {
    __shared__ int bad;
    if (threadIdx.x == 0) bad = 0;
    __syncthreads();
    for (int i = threadIdx.x; i < 1024; i += 256)
        if (edge[i] > 0xFFFFFFFFull) bad = 1;
    __syncthreads();
    if (threadIdx.x == 0) g_is64 = bad ? 0 : 1;
}

// ---------------- prepP: P vectors (1 block per k-row) -----------------------
__global__ void __launch_bounds__(256) prepP(
    const float* __restrict__ W1, const float* __restrict__ a1s, const float* __restrict__ a1d,
    const float* __restrict__ W2, const float* __restrict__ a2s, const float* __restrict__ a2d)
{
    int k = blockIdx.x;
    int wid = threadIdx.x >> 5, lane = threadIdx.x & 31;
    {
        int h = wid & 3;
        const float* w = W1 + (size_t)k * (4 * FDIM) + h * FDIM;
        const float* a = (wid < 4 ? a1s : a1d) + h * FDIM;
        float s = 0.f;
        for (int i = lane; i < FDIM; i += 32) s += w[i] * a[i];
#pragma unroll
        for (int o = 16; o; o >>= 1) s += __shfl_down_sync(0xffffffffu, s, o);
        if (lane == 0) g_P1[k * 8 + wid] = s;
    }
    if (wid < 2) {
        const float* w = W2 + (size_t)k * FDIM;
        const float* a = (wid == 0) ? a2s : a2d;
        float s = 0.f;
        for (int i = lane; i < FDIM; i += 32) s += w[i] * a[i];
#pragma unroll
        for (int o = 16; o; o >>= 1) s += __shfl_down_sync(0xffffffffu, s, o);
        if (lane == 0) g_P2[k * 2 + wid] = s;
    }
}

// ---------------- prepW: W1 repack (x0.25) + W2 convert to fp16 --------------
#define PREP_WELEM ((size_t)5 * FDIM * FDIM)
#define PREP_WBLK ((int)((PREP_WELEM + 255) / 256))

__global__ void __launch_bounds__(256) prepW(const float* __restrict__ W1,
                                             const float* __restrict__ W2)
{
    const size_t S1 = (size_t)4 * FDIM * FDIM;
    size_t idx = (size_t)blockIdx.x * 256 + threadIdx.x;
    if (idx < S1) {
        int j = (int)(idx % FDIM);
        int r = (int)(idx / FDIM);     // h*768 + k
        int h = r / FDIM, k = r % FDIM;
        g_W1ph[idx] = __float2half(0.25f * W1[(size_t)k * (4 * FDIM) + h * FDIM + j]);
    } else if (idx < PREP_WELEM) {
        size_t i2 = idx - S1;
        g_W2rh[i2] = __float2half(W2[i2]);
    }
}

// ---------------- e1 = x @ P1, also emit x as fp16 (2 nodes/warp) ------------
__global__ void __launch_bounds__(256) compute_e8(
    const float* __restrict__ x, const float* __restrict__ P,
    float* __restrict__ e, __half* __restrict__ xh)
{
    __shared__ __align__(16) float sP[8 * FDIM];   // transposed [j][k]
    for (int i = threadIdx.x; i < 8 * FDIM; i += 256) {
        int j = i / FDIM, k = i % FDIM;
        sP[j * FDIM + k] = P[k * 8 + j];
    }
    __syncthreads();
    const float4* sP4 = (const float4*)sP;         // [8][192]
    int warp = threadIdx.x >> 5, lane = threadIdx.x & 31;
    int n0 = (blockIdx.x * 8 + warp) * 2;          // grid = 1024 -> 2 nodes/warp
    const float4* xr0 = (const float4*)(x + (size_t)n0 * FDIM);
    const float4* xr1 = (const float4*)(x + (size_t)(n0 + 1) * FDIM);
    uint2* xw0 = (uint2*)(xh + (size_t)n0 * FDIM);
    uint2* xw1 = (uint2*)(xh + (size_t)(n0 + 1) * FDIM);
    float acc0[8], acc1[8];
#pragma unroll
    for (int j = 0; j < 8; j++) { acc0[j] = 0.f; acc1[j] = 0.f; }
#pragma unroll
    for (int it = 0; it < 6; it++) {
        float4 v0 = xr0[lane + it * 32];
        float4 v1 = xr1[lane + it * 32];
        {
            __half2 h0 = __floats2half2_rn(v0.x, v0.y);
            __half2 h1 = __floats2half2_rn(v0.z, v0.w);
            uint2 hw; hw.x = *(uint32_t*)&h0; hw.y = *(uint32_t*)&h1;
            xw0[lane + it * 32] = hw;
        }
        {
            __half2 h0 = __floats2half2_rn(v1.x, v1.y);
            __half2 h1 = __floats2half2_rn(v1.z, v1.w);
            uint2 hw; hw.x = *(uint32_t*)&h0; hw.y = *(uint32_t*)&h1;
            xw1[lane + it * 32] = hw;
        }
#pragma unroll
        for (int j = 0; j < 8; j++) {
            float4 p = sP4[j * 192 + lane + it * 32];   // one LDS feeds 2 nodes
            acc0[j] += v0.x * p.x + v0.y * p.y + v0.z * p.z + v0.w * p.w;
            acc1[j] += v1.x * p.x + v1.y * p.y + v1.z * p.z + v1.w * p.w;
        }
    }
#pragma unroll
    for (int j = 0; j < 8; j++) {
        float s0 = acc0[j], s1 = acc1[j];
#pragma unroll
        for (int o = 16; o; o >>= 1) {
            s0 += __shfl_down_sync(0xffffffffu, s0, o);
            s1 += __shfl_down_sync(0xffffffffu, s1, o);
        }
        if (lane == 0) {
            e[(size_t)n0 * 8 + j] = s0;
            e[(size_t)(n0 + 1) * 8 + j] = s1;
        }
    }
}

// ---------------- layer-1 softmax + weighted gather: 4 nodes/block -----------
__global__ void __launch_bounds__(384) aggregate1(
    const __half* __restrict__ x, const float* __restrict__ e,
    const void* __restrict__ edge, __half* __restrict__ agg)
{
    int n0 = blockIdx.x * 4;
    __shared__ int   s_src[4][5];
    __shared__ float s_alpha[4][4][5];
    int tid = threadIdx.x;
    if (tid < 20) {
        int node = tid / 5, k = tid % 5;
        int n = n0 + node;
        int sv = n;
        if (k < 4) {
            sv = g_is64 ? (int)((const long long*)edge)[(size_t)DEG * n + k]
                        : ((const int*)edge)[DEG * n + k];
        }
        s_src[node][k] = sv;
    }
    __syncthreads();
    if (tid < 16) {
        int node = tid >> 2, h = tid & 3;
        int n = n0 + node;
        float ed = e[(size_t)n * 8 + 4 + h];
        float l[5];
#pragma unroll
        for (int k = 0; k < 5; k++) {
            float v = e[(size_t)s_src[node][k] * 8 + h] + ed;
            l[k] = v >= 0.f ? v : 0.2f * v;
        }
        float m = l[0];
#pragma unroll
        for (int k = 1; k < 5; k++) m = fmaxf(m, l[k]);
        float s = 0.f;
#pragma unroll
        for (int k = 0; k < 5; k++) { l[k] = expf(l[k] - m); s += l[k]; }
        float inv = 1.f / (s + 1e-16f);
#pragma unroll
        for (int k = 0; k < 5; k++) s_alpha[node][h][k] = l[k] * inv;
    }
    __syncthreads();
    int d2 = tid;  // 384 threads x 2 dims = 768
#pragma unroll
    for (int node = 0; node < 4; node++) {
        int n = n0 + node;
        float2 xv[5];
#pragma unroll
        for (int k = 0; k < 5; k++)
            xv[k] = __half22float2(
                ((const __half2*)(x + (size_t)s_src[node][k] * FDIM))[d2]);
#pragma unroll
        for (int h = 0; h < 4; h++) {
            float ax = 0.f, ay = 0.f;
#pragma unroll
            for (int k = 0; k < 5; k++) {
                float al = s_alpha[node][h][k];
                ax += al * xv[k].x;
                ay += al * xv[k].y;
            }
            ((__half2*)(agg + ((size_t)n * 4 + h) * FDIM))[d2] =
                __floats2half2_rn(ax, ay);
        }
    }
}

// ---------------- fp16 mma.sync persistent GEMM (BK=32, 4-stage) -------------
#define BM 128
#define BN 128
#define BK 32
#define ASTRH 40
#define BSTRH 136
#define A_STG (BM * ASTRH)
#define B_STG (BK * BSTRH)
#define NSTAGE 4
#define GEMM_SMEM (NSTAGE * (A_STG + B_STG) * 2)

__global__ void __launch_bounds__(256, 2) gemm_fp16(
    const __half* __restrict__ A, const __half* __restrict__ B,
    const float* __restrict__ bias, __half* __restrict__ C,
    int Nn, int K, int ntiles, int T)
{
    extern __shared__ __half hsm[];
    uint32_t asb = smem_u32(hsm);
    uint32_t bsb = asb + NSTAGE * A_STG * 2;

    int tid = threadIdx.x;
    int lane = tid & 31, wid = tid >> 5;
    int warpM = wid & 1, warpN = wid >> 1;
    int g = lane >> 2, tg = lane & 3;
    int KT = K / BK;

    int ar = tid >> 2, ac8 = (tid & 3) * 8;
    int br = tid >> 4, bc8 = (tid & 15) * 8;

    auto load_stage = [&](int s, int k0, int bm, int bn) {
#pragma unroll
        for (int t = 0; t < 2; t++) {
            int r = ar + t * 64;
            cp16(asb + (uint32_t)(s * A_STG + r * ASTRH + ac8) * 2,
                 A + (size_t)(bm + r) * K + k0 + ac8);
        }
#pragma unroll
        for (int t = 0; t < 2; t++) {
            int r = br + t * 16;
            cp16(bsb + (uint32_t)(s * B_STG + r * BSTRH + bc8) * 2,
                 B + (size_t)(k0 + r) * Nn + bn + bc8);
        }
        asm volatile("cp.async.commit_group;");
    };

    uint32_t a_off = (uint32_t)((warpM * 64 + (lane & 15)) * ASTRH + (lane >> 4) * 8);
    uint32_t b_off = (uint32_t)((lane & 15) * BSTRH + warpN * 32 + (lane >> 4) * 8);

    int t0 = blockIdx.x;
    if (t0 >= T) return;
    {
        int bm = (t0 / ntiles) * BM, bn = (t0 % ntiles) * BN;
        load_stage(0, 0, bm, bn);
        load_stage(1, BK, bm, bn);
        load_stage(2, 2 * BK, bm, bn);
    }

    for (int t = t0; t < T; t += gridDim.x) {
        int bm = (t / ntiles) * BM, bn = (t % ntiles) * BN;
        int tn = t + gridDim.x; if (tn >= T) tn = t;
        int bm2 = (tn / ntiles) * BM, bn2 = (tn % ntiles) * BN;

        float acc[4][4][4];
#pragma unroll
        for (int i = 0; i < 4; i++)
#pragma unroll
            for (int j = 0; j < 4; j++)
#pragma unroll
                for (int r = 0; r < 4; r++) acc[i][j][r] = 0.f;

        for (int kt = 0; kt < KT; kt++) {
            asm volatile("cp.async.wait_group 2;");
            __syncthreads();

            int pf = kt + NSTAGE - 1;
            if (pf < KT) load_stage(pf & 3, pf * BK, bm, bn);
            else         load_stage(pf & 3, (pf - KT) * BK, bm2, bn2);

            int buf = kt & 3;
            uint32_t a_base = asb + (buf * A_STG + a_off) * 2;
            uint32_t b_base = bsb + (buf * B_STG + b_off) * 2;
#pragma unroll
            for (int ks = 0; ks < 2; ks++) {
                uint32_t af[4][4], bf[2][4];
#pragma unroll
                for (int mt = 0; mt < 4; mt++)
                    ldsm_x4(af[mt], a_base + (uint32_t)(mt * 16 * ASTRH + ks * 16) * 2);
#pragma unroll
                for (int np = 0; np < 2; np++)
                    ldsm_x4_t(bf[np], b_base + (uint32_t)(ks * 16 * BSTRH + np * 16) * 2);
#pragma unroll
                for (int mt = 0; mt < 4; mt++)
#pragma unroll
                    for (int np = 0; np < 2; np++) {
                        mma_f16(acc[mt][np * 2 + 0], af[mt], &bf[np][0]);
                        mma_f16(acc[mt][np * 2 + 1], af[mt], &bf[np][2]);
                    }
            }
        }

#pragma unroll
        for (int mt = 0; mt < 4; mt++) {
            int row = bm + warpM * 64 + mt * 16 + g;
#pragma unroll
            for (int nt = 0; nt < 4; nt++) {
                int col = bn + warpN * 32 + nt * 8 + tg * 2;
                float b0 = bias[col], b1 = bias[col + 1];
                *(__half2*)(C + (size_t)row * Nn + col) =
                    __floats2half2_rn(acc[mt][nt][0] + b0, acc[mt][nt][1] + b1);
                *(__half2*)(C + (size_t)(row + 8) * Nn + col) =
                    __floats2half2_rn(acc[mt][nt][2] + b0, acc[mt][nt][3] + b1);
            }
        }
    }
    asm volatile("cp.async.wait_group 0;");
}

// ---------------- elu + LN + fused e2 logits (256 thr; R13 form) -------------
__global__ void __launch_bounds__(256) elu_ln_e2(
    const __half* __restrict__ in, const float* __restrict__ gamma,
    const float* __restrict__ beta, const float* __restrict__ P2,
    __half* __restrict__ out, float* __restrict__ e2)
{
    __shared__ float red[8];
    __shared__ float s_mu, s_w;
    int n = blockIdx.x;
    int tid = threadIdx.x;
    const __half* row = in + (size_t)n * FDIM;
    float y[3];
    float s = 0.f;
#pragma unroll
    for (int i = 0; i < 3; i++) {
        float v = __half2float(row[tid + i * 256]);
        y[i] = v > 0.f ? v : expm1f(v);
        s += y[i];
    }
    float tot = block_reduce_256(s, red);
    if (tid == 0) s_mu = tot * (1.f / FDIM);
    __syncthreads();
    float mu = s_mu;
    float q = 0.f;
#pragma unroll
    for (int i = 0; i < 3; i++) { float d = y[i] - mu; q += d * d; }
    float totq = block_reduce_256(q, red);
    if (tid == 0) s_w = rsqrtf(totq * (1.f / FDIM) + 1e-5f);
    __syncthreads();
    float w = s_w;
    float o3[3];
#pragma unroll
    for (int i = 0; i < 3; i++) {
        int d = tid + i * 256;
        o3[i] = (y[i] - mu) * w * gamma[d] + beta[d];
        out[(size_t)n * FDIM + d] = __float2half(o3[i]);
    }
    float s0 = 0.f, s1 = 0.f;
#pragma unroll
    for (int i = 0; i < 3; i++) {
        int d = tid + i * 256;
        s0 += o3[i] * P2[d * 2 + 0];
        s1 += o3[i] * P2[d * 2 + 1];
    }
    __syncthreads();
    float t0 = block_reduce_256(s0, red);
    if (tid == 0) e2[(size_t)n * 2 + 0] = t0;
    __syncthreads();
    float t1 = block_reduce_256(s1, red);
    if (tid == 0) e2[(size_t)n * 2 + 1] = t1;
}

// ---------------- fused layer-2 epilogue: gather(pre2) + bias + elu + LN + clip
__global__ void __launch_bounds__(384) agg2_ln_f(
    const __half* __restrict__ pre, const float* __restrict__ e2,
    const void* __restrict__ edge, const float* __restrict__ b2,
    const float* __restrict__ gamma, const float* __restrict__ beta,
    float* __restrict__ out)
{
    __shared__ int   s_src[5];
    __shared__ float s_alpha[5];
    __shared__ float red[12];
    __shared__ float s_mu, s_w;
    int n = blockIdx.x;
    int tid = threadIdx.x;
    if (tid < 5) {
        int sv = n;
        if (tid < 4) {
            sv = g_is64 ? (int)((const long long*)edge)[(size_t)DEG * n + tid]
                        : ((const int*)edge)[DEG * n + tid];
        }
        s_src[tid] = sv;
    }
    __syncthreads();
    if (tid == 0) {
        float ed = e2[(size_t)n * 2 + 1];
        float l[5];
#pragma unroll
        for (int k = 0; k < 5; k++) {
            float v = e2[(size_t)s_src[k] * 2 + 0] + ed;
            l[k] = v >= 0.f ? v : 0.2f * v;
        }
        float m = l[0];
#pragma unroll
        for (int k = 1; k < 5; k++) m = fmaxf(m, l[k]);
        float s = 0.f;
#pragma unroll
        for (int k = 0; k < 5; k++) { l[k] = expf(l[k] - m); s += l[k]; }
        float inv = 1.f / (s + 1e-16f);
#pragma unroll
        for (int k = 0; k < 5; k++) s_alpha[k] = l[k] * inv;
    }
    __syncthreads();
    int d2 = tid;
    float ax = 0.f, ay = 0.f;
#pragma unroll
    for (int k = 0; k < 5; k++) {
        float2 v = __half22float2(((const __half2*)(pre + (size_t)s_src[k] * FDIM))[d2]);
        float al = s_alpha[k];
        ax += al * v.x;
        ay += al * v.y;
    }
    ax += b2[d2 * 2 + 0];
    ay += b2[d2 * 2 + 1];
    float yx = ax > 0.f ? ax : expm1f(ax);
    float yy = ay > 0.f ? ay : expm1f(ay);
    float tot = block_reduce_384(yx + yy, red);
    if (tid == 0) s_mu = tot * (1.f / FDIM);
    __syncthreads();
    float mu = s_mu;
    float dx = yx - mu, dy = yy - mu;
    float totq = block_reduce_384(dx * dx + dy * dy, red);
    if (tid == 0) s_w = rsqrtf(totq * (1.f / FDIM) + 1e-5f);
    __syncthreads();
    float w = s_w;
    float ox = dx * w * gamma[d2 * 2 + 0] + beta[d2 * 2 + 0];
    float oy = dy * w * gamma[d2 * 2 + 1] + beta[d2 * 2 + 1];
    ox = fminf(fmaxf(ox, -10000.f), 10000.f);
    oy = fminf(fmaxf(oy, -10000.f), 10000.f);
    ((float2*)(out + (size_t)n * FDIM))[d2] = make_float2(ox, oy);
}

// ---------------- launch ------------------------------------------------------
extern "C" void kernel_launch(void* const* d_in, const int* in_sizes, int n_in,
                              void* d_out, int out_size)
{
    const float* x   = (const float*)d_in[0];
    const void*  ei  = d_in[1];
    const float* W1  = (const float*)d_in[2];
    const float* a1s = (const float*)d_in[3];
    const float* a1d = (const float*)d_in[4];
    const float* b1  = (const float*)d_in[5];
    const float* W2  = (const float*)d_in[6];
    const float* a2s = (const float*)d_in[7];
    const float* a2d = (const float*)d_in[8];
    const float* b2  = (const float*)d_in[9];
    const float* gm  = (const float*)d_in[10];
    const float* bt  = (const float*)d_in[11];
    float* out = (float*)d_out;

    float *p1, *p2, *e1, *e2, *zb;
    __half *w1ph, *w2rh, *xh, *agg1h, *preh, *x1h;
    cudaGetSymbolAddress((void**)&p1,    g_P1);
    cudaGetSymbolAddress((void**)&p2,    g_P2);
    cudaGetSymbolAddress((void**)&zb,    g_zerob);
    cudaGetSymbolAddress((void**)&w1ph,  g_W1ph);
    cudaGetSymbolAddress((void**)&w2rh,  g_W2rh);
    cudaGetSymbolAddress((void**)&e1,    g_e1);
    cudaGetSymbolAddress((void**)&e2,    g_e2);
    cudaGetSymbolAddress((void**)&xh,    g_xh);
    cudaGetSymbolAddress((void**)&agg1h, g_agg1h);
    cudaGetSymbolAddress((void**)&preh,  g_preh);
    cudaGetSymbolAddress((void**)&x1h,   g_x1h);

    cudaFuncSetAttribute(gemm_fp16, cudaFuncAttributeMaxDynamicSharedMemorySize, GEMM_SMEM);
    cudaFuncSetAttribute(gemm_fp16, cudaFuncAttributePreferredSharedMemoryCarveout, 100);

    const int T = (NNODES / BM) * (FDIM / BN);   // 768 tiles

    probe<<<1, 256>>>((const unsigned long long*)ei);                         // 1
    prepP<<<FDIM, 256>>>(W1, a1s, a1d, W2, a2s, a2d);                         // 2
    prepW<<<PREP_WBLK, 256>>>(W1, W2);                                        // 3

    // layer 1 (aggregate-then-project; head-mean folded into W1p)
    compute_e8<<<1024, 256>>>(x, p1, e1, xh);                                 // 4 (ncu)
    aggregate1<<<NNODES / 4, 384>>>(xh, e1, ei, agg1h);                       // 5
    gemm_fp16<<<296, 256, GEMM_SMEM>>>(agg1h, w1ph, b1, preh,                 // 6
                                       FDIM, 4 * FDIM, FDIM / BN, T);
    elu_ln_e2<<<NNODES, 256>>>(preh, gm, bt, p2, x1h, e2);                    // 7

    // layer 2 (project-then-aggregate; bias folded into fused epilogue)
    gemm_fp16<<<296, 256, GEMM_SMEM>>>(x1h, w2rh, zb, preh,                   // 8
                                       FDIM, FDIM, FDIM / BN, T);
    agg2_ln_f<<<NNODES, 384>>>(preh, e2, ei, b2, gm, bt, out);                // 9
}

// round 16
// speedup vs baseline: 1.0751x; 1.0467x over previous
#include <cuda_runtime.h>
#include <cuda_fp16.h>
#include <cstdint>
#include <cstddef>

#define NNODES 16384
#define FDIM   768
#define DEG    4

// ---------------- scratch (device globals; no allocation allowed) ----------
__device__ float  g_P1[FDIM * 8];
__device__ float  g_P2[FDIM * 2];
__device__ float  g_zerob[FDIM];                      // zero bias (static-zeroed)
__device__ __half g_W1ph[(size_t)4 * FDIM * FDIM];    // [3072,768] B GEMM1 (x0.25, fp16)
__device__ __half g_W2rh[(size_t)FDIM * FDIM];        // [768,768]  B GEMM2 (fp16)
__device__ float  g_e1[(size_t)NNODES * 8];
__device__ float  g_e2[(size_t)NNODES * 2];
__device__ __half g_xh[(size_t)NNODES * FDIM];        // x in fp16 (emitted by compute_e8)
__device__ __half g_agg1h[(size_t)NNODES * 4 * FDIM]; // [N,3072] A GEMM1 (fp16)
__device__ __half g_preh[(size_t)NNODES * FDIM];      // GEMM output (fp16)
__device__ __half g_x1h[(size_t)NNODES * FDIM];       // layer-1 output (fp16)
__device__ int    g_is64;

// ---------------- helpers ---------------------------------------------------
__device__ __forceinline__ uint32_t smem_u32(const void* p) {
    uint32_t a;
    asm("{ .reg .u64 t; cvta.to.shared.u64 t, %1; cvt.u32.u64 %0, t; }" : "=r"(a) : "l"(p));
    return a;
}

__device__ __forceinline__ void cp16(uint32_t s, const void* g) {
    asm volatile("cp.async.cg.shared.global [%0], [%1], 16;" :: "r"(s), "l"(g));
}

__device__ __forceinline__ void ldsm_x4(uint32_t* r, uint32_t addr) {
    asm volatile("ldmatrix.sync.aligned.m8n8.x4.shared.b16 {%0,%1,%2,%3}, [%4];"
                 : "=r"(r[0]), "=r"(r[1]), "=r"(r[2]), "=r"(r[3]) : "r"(addr));
}

__device__ __forceinline__ void ldsm_x4_t(uint32_t* r, uint32_t addr) {
    asm volatile("ldmatrix.sync.aligned.m8n8.x4.trans.shared.b16 {%0,%1,%2,%3}, [%4];"
                 : "=r"(r[0]), "=r"(r[1]), "=r"(r[2]), "=r"(r[3]) : "r"(addr));
}

__device__ __forceinline__ void mma_f16(float* d, const uint32_t* a, const uint32_t* b) {
    asm volatile(
        "mma.sync.aligned.m16n8k16.row.col.f32.f16.f16.f32 "
        "{%0,%1,%2,%3}, {%4,%5,%6,%7}, {%8,%9}, {%0,%1,%2,%3};"
        : "+f"(d[0]), "+f"(d[1]), "+f"(d[2]), "+f"(d[3])
        : "r"(a[0]), "r"(a[1]), "r"(a[2]), "r"(a[3]), "r"(b[0]), "r"(b[1]));
}

// dual-value block reduction, 256 threads (8 warps); valid in thread 0
__device__ __forceinline__ float2 block_reduce2_256(float a, float b, float2* red) {
#pragma unroll
    for (int o = 16; o; o >>= 1) {
        a += __shfl_down_sync(0xffffffffu, a, o);
        b += __shfl_down_sync(0xffffffffu, b, o);
    }
    if ((threadIdx.x & 31) == 0) red[threadIdx.x >> 5] = make_float2(a, b);
    __syncthreads();
    float2 r = make_float2(0.f, 0.f);
    if (threadIdx.x < 8) r = red[threadIdx.x];
    if (threadIdx.x < 32) {
#pragma unroll
        for (int o = 4; o; o >>= 1) {
            r.x += __shfl_down_sync(0xffu, r.x, o);
            r.y += __shfl_down_sync(0xffu, r.y, o);
        }
    }
    return r;
}

// dual-value block reduction, 384 threads (12 warps); valid in thread 0
__device__ __forceinline__ float2 block_reduce2_384(float a, float b, float2* red) {
#pragma unroll
    for (int o = 16; o; o >>= 1) {
        a += __shfl_down_sync(0xffffffffu, a, o);
        b += __shfl_down_sync(0xffffffffu, b, o);
    }
    if ((threadIdx.x & 31) == 0) red[threadIdx.x >> 5] = make_float2(a, b);
    __syncthreads();
    float2 r = make_float2(0.f, 0.f);
    if (threadIdx.x < 12) r = red[threadIdx.x];
    if (threadIdx.x < 32) {
#pragma unroll
        for (int o = 8; o; o >>= 1) {
            r.x += __shfl_down_sync(0xffffffffu, r.x, o);
            r.y += __shfl_down_sync(0xffffffffu, r.y, o);
        }
    }
    return r;
}

// ---------------- merged prep: probe + P vectors + W repack ------------------
#define PREP_WELEM ((size_t)5 * FDIM * FDIM)
#define PREP_WBLK ((int)((PREP_WELEM + 255) / 256))
#define PREP_GRID (1 + FDIM + PREP_WBLK)

__global__ void __launch_bounds__(256) prep(
    const float* __restrict__ W1, const float* __restrict__ a1s, const float* __restrict__ a1d,
    const float* __restrict__ W2, const float* __restrict__ a2s, const float* __restrict__ a2d,
    const unsigned long long* __restrict__ edge)
{
    int b = blockIdx.x;
    if (b == 0) {
        __shared__ int bad;
        if (threadIdx.x == 0) bad = 0;
        __syncthreads();
        for (int i = threadIdx.x; i < 1024; i += 256)
            if (edge[i] > 0xFFFFFFFFull) bad = 1;
        __syncthreads();
        if (threadIdx.x == 0) g_is64 = bad ? 0 : 1;
        return;
    }
    if (b <= FDIM) {
        int k = b - 1;
        int wid = threadIdx.x >> 5, lane = threadIdx.x & 31;
        {
            int h = wid & 3;
            const float* w = W1 + (size_t)k * (4 * FDIM) + h * FDIM;
            const float* a = (wid < 4 ? a1s : a1d) + h * FDIM;
            float s = 0.f;
            for (int i = lane; i < FDIM; i += 32) s += w[i] * a[i];
#pragma unroll
            for (int o = 16; o; o >>= 1) s += __shfl_down_sync(0xffffffffu, s, o);
            if (lane == 0) g_P1[k * 8 + wid] = s;
        }
        if (wid < 2) {
            const float* w = W2 + (size_t)k * FDIM;
            const float* a = (wid == 0) ? a2s : a2d;
            float s = 0.f;
            for (int i = lane; i < FDIM; i += 32) s += w[i] * a[i];
#pragma unroll
            for (int o = 16; o; o >>= 1) s += __shfl_down_sync(0xffffffffu, s, o);
            if (lane == 0) g_P2[k * 2 + wid] = s;
        }
        return;
    }
    const size_t S1 = (size_t)4 * FDIM * FDIM;
    size_t idx = (size_t)(b - 1 - FDIM) * 256 + threadIdx.x;
    if (idx < S1) {
        int j = (int)(idx % FDIM);
        int r = (int)(idx / FDIM);     // h*768 + k
        int h = r / FDIM, k = r % FDIM;
        g_W1ph[idx] = __float2half(0.25f * W1[(size_t)k * (4 * FDIM) + h * FDIM + j]);
    } else if (idx < PREP_WELEM) {
        size_t i2 = idx - S1;
        g_W2rh[i2] = __float2half(W2[i2]);
    }
}

// ---------------- e1 = x @ P1, also emit x as fp16 (2 nodes/warp) ------------
__global__ void __launch_bounds__(256) compute_e8(
    const float* __restrict__ x, const float* __restrict__ P,
    float* __restrict__ e, __half* __restrict__ xh)
{
    __shared__ __align__(16) float sP[8 * FDIM];   // transposed [j][k]
    for (int i = threadIdx.x; i < 8 * FDIM; i += 256) {
        int j = i / FDIM, k = i % FDIM;
        sP[j * FDIM + k] = P[k * 8 + j];
    }
    __syncthreads();
    const float4* sP4 = (const float4*)sP;         // [8][192]
    int warp = threadIdx.x >> 5, lane = threadIdx.x & 31;
    int n0 = (blockIdx.x * 8 + warp) * 2;          // grid = 1024 -> 2 nodes/warp
    const float4* xr0 = (const float4*)(x + (size_t)n0 * FDIM);
    const float4* xr1 = (const float4*)(x + (size_t)(n0 + 1) * FDIM);
    uint2* xw0 = (uint2*)(xh + (size_t)n0 * FDIM);
    uint2* xw1 = (uint2*)(xh + (size_t)(n0 + 1) * FDIM);
    float acc0[8], acc1[8];
#pragma unroll
    for (int j = 0; j < 8; j++) { acc0[j] = 0.f; acc1[j] = 0.f; }
#pragma unroll
    for (int it = 0; it < 6; it++) {
        float4 v0 = xr0[lane + it * 32];
        float4 v1 = xr1[lane + it * 32];
        {
            __half2 h0 = __floats2half2_rn(v0.x, v0.y);
            __half2 h1 = __floats2half2_rn(v0.z, v0.w);
            uint2 hw; hw.x = *(uint32_t*)&h0; hw.y = *(uint32_t*)&h1;
            xw0[lane + it * 32] = hw;
        }
        {
            __half2 h0 = __floats2half2_rn(v1.x, v1.y);
            __half2 h1 = __floats2half2_rn(v1.z, v1.w);
            uint2 hw; hw.x = *(uint32_t*)&h0; hw.y = *(uint32_t*)&h1;
            xw1[lane + it * 32] = hw;
        }
#pragma unroll
        for (int j = 0; j < 8; j++) {
            float4 p = sP4[j * 192 + lane + it * 32];   // one LDS feeds 2 nodes
            acc0[j] += v0.x * p.x + v0.y * p.y + v0.z * p.z + v0.w * p.w;
            acc1[j] += v1.x * p.x + v1.y * p.y + v1.z * p.z + v1.w * p.w;
        }
    }
#pragma unroll
    for (int j = 0; j < 8; j++) {
        float s0 = acc0[j], s1 = acc1[j];
#pragma unroll
        for (int o = 16; o; o >>= 1) {
            s0 += __shfl_down_sync(0xffffffffu, s0, o);
            s1 += __shfl_down_sync(0xffffffffu, s1, o);
        }
        if (lane == 0) {
            e[(size_t)n0 * 8 + j] = s0;
            e[(size_t)(n0 + 1) * 8 + j] = s1;
        }
    }
}

// ---------------- layer-1 softmax + weighted gather: 8 nodes/block -----------
__global__ void __launch_bounds__(384) aggregate1(
    const __half* __restrict__ x, const float* __restrict__ e,
    const void* __restrict__ edge, __half* __restrict__ agg)
{
    int n0 = blockIdx.x * 8;
    __shared__ int   s_src[8][5];
    __shared__ float s_alpha[8][4][5];
    int tid = threadIdx.x;
    if (tid < 40) {
        int node = tid / 5, k = tid % 5;
        int n = n0 + node;
        int sv = n;
        if (k < 4) {
            sv = g_is64 ? (int)((const long long*)edge)[(size_t)DEG * n + k]
                        : ((const int*)edge)[DEG * n + k];
        }
        s_src[node][k] = sv;
    }
    __syncthreads();
    if (tid < 32) {
        int node = tid >> 2, h = tid & 3;
        int n = n0 + node;
        float ed = e[(size_t)n * 8 + 4 + h];
        float l[5];
#pragma unroll
        for (int k = 0; k < 5; k++) {
            float v = e[(size_t)s_src[node][k] * 8 + h] + ed;
            l[k] = v >= 0.f ? v : 0.2f * v;
        }
        float m = l[0];
#pragma unroll
        for (int k = 1; k < 5; k++) m = fmaxf(m, l[k]);
        float s = 0.f;
#pragma unroll
        for (int k = 0; k < 5; k++) { l[k] = expf(l[k] - m); s += l[k]; }
        float inv = 1.f / (s + 1e-16f);
#pragma unroll
        for (int k = 0; k < 5; k++) s_alpha[node][h][k] = l[k] * inv;
    }
    __syncthreads();
    int d2 = tid;  // 384 threads x 2 dims = 768
#pragma unroll
    for (int node = 0; node < 8; node++) {
        int n = n0 + node;
        float2 xv[5];
#pragma unroll
        for (int k = 0; k < 5; k++)
            xv[k] = __half22float2(
                ((const __half2*)(x + (size_t)s_src[node][k] * FDIM))[d2]);
#pragma unroll
        for (int h = 0; h < 4; h++) {
            float ax = 0.f, ay = 0.f;
#pragma unroll
            for (int k = 0; k < 5; k++) {
                float al = s_alpha[node][h][k];
                ax += al * xv[k].x;
                ay += al * xv[k].y;
            }
            ((__half2*)(agg + ((size_t)n * 4 + h) * FDIM))[d2] =
                __floats2half2_rn(ax, ay);
        }
    }
}

// ---------------- fp16 mma.sync persistent GEMM (BK=32, 4-stage) -------------
#define BM 128
#define BN 128
#define BK 32
#define ASTRH 40
#define BSTRH 136
#define A_STG (BM * ASTRH)
#define B_STG (BK * BSTRH)
#define NSTAGE 4
#define GEMM_SMEM (NSTAGE * (A_STG + B_STG) * 2)

__global__ void __launch_bounds__(256, 2) gemm_fp16(
    const __half* __restrict__ A, const __half* __restrict__ B,
    const float* __restrict__ bias, __half* __restrict__ C,
    int Nn, int K, int ntiles, int T)
{
    extern __shared__ __half hsm[];
    uint32_t asb = smem_u32(hsm);
    uint32_t bsb = asb + NSTAGE * A_STG * 2;

    int tid = threadIdx.x;
    int lane = tid & 31, wid = tid >> 5;
    int warpM = wid & 1, warpN = wid >> 1;
    int g = lane >> 2, tg = lane & 3;
    int KT = K / BK;

    int ar = tid >> 2, ac8 = (tid & 3) * 8;
    int br = tid >> 4, bc8 = (tid & 15) * 8;

    auto load_stage = [&](int s, int k0, int bm, int bn) {
#pragma unroll
        for (int t = 0; t < 2; t++) {
            int r = ar + t * 64;
            cp16(asb + (uint32_t)(s * A_STG + r * ASTRH + ac8) * 2,
                 A + (size_t)(bm + r) * K + k0 + ac8);
        }
#pragma unroll
        for (int t = 0; t < 2; t++) {
            int r = br + t * 16;
            cp16(bsb + (uint32_t)(s * B_STG + r * BSTRH + bc8) * 2,
                 B + (size_t)(k0 + r) * Nn + bn + bc8);
        }
        asm volatile("cp.async.commit_group;");
    };

    uint32_t a_off = (uint32_t)((warpM * 64 + (lane & 15)) * ASTRH + (lane >> 4) * 8);
    uint32_t b_off = (uint32_t)((lane & 15) * BSTRH + warpN * 32 + (lane >> 4) * 8);

    int t0 = blockIdx.x;
    if (t0 >= T) return;
    {
        int bm = (t0 / ntiles) * BM, bn = (t0 % ntiles) * BN;
        load_stage(0, 0, bm, bn);
        load_stage(1, BK, bm, bn);
        load_stage(2, 2 * BK, bm, bn);
    }

    for (int t = t0; t < T; t += gridDim.x) {
        int bm = (t / ntiles) * BM, bn = (t % ntiles) * BN;
        int tn = t + gridDim.x; if (tn >= T) tn = t;
        int bm2 = (tn / ntiles) * BM, bn2 = (tn % ntiles) * BN;

        float acc[4][4][4];
#pragma unroll
        for (int i = 0; i < 4; i++)
#pragma unroll
            for (int j = 0; j < 4; j++)
#pragma unroll
                for (int r = 0; r < 4; r++) acc[i][j][r] = 0.f;

        for (int kt = 0; kt < KT; kt++) {
            asm volatile("cp.async.wait_group 2;");
            __syncthreads();

            int pf = kt + NSTAGE - 1;
            if (pf < KT) load_stage(pf & 3, pf * BK, bm, bn);
            else         load_stage(pf & 3, (pf - KT) * BK, bm2, bn2);

            int buf = kt & 3;
            uint32_t a_base = asb + (buf * A_STG + a_off) * 2;
            uint32_t b_base = bsb + (buf * B_STG + b_off) * 2;
#pragma unroll
            for (int ks = 0; ks < 2; ks++) {
                uint32_t af[4][4], bf[2][4];
#pragma unroll
                for (int mt = 0; mt < 4; mt++)
                    ldsm_x4(af[mt], a_base + (uint32_t)(mt * 16 * ASTRH + ks * 16) * 2);
#pragma unroll
                for (int np = 0; np < 2; np++)
                    ldsm_x4_t(bf[np], b_base + (uint32_t)(ks * 16 * BSTRH + np * 16) * 2);
#pragma unroll
                for (int mt = 0; mt < 4; mt++)
#pragma unroll
                    for (int np = 0; np < 2; np++) {
                        mma_f16(acc[mt][np * 2 + 0], af[mt], &bf[np][0]);
                        mma_f16(acc[mt][np * 2 + 1], af[mt], &bf[np][2]);
                    }
            }
        }

#pragma unroll
        for (int mt = 0; mt < 4; mt++) {
            int row = bm + warpM * 64 + mt * 16 + g;
#pragma unroll
            for (int nt = 0; nt < 4; nt++) {
                int col = bn + warpN * 32 + nt * 8 + tg * 2;
                float b0 = bias[col], b1 = bias[col + 1];
                *(__half2*)(C + (size_t)row * Nn + col) =
                    __floats2half2_rn(acc[mt][nt][0] + b0, acc[mt][nt][1] + b1);
                *(__half2*)(C + (size_t)(row + 8) * Nn + col) =
                    __floats2half2_rn(acc[mt][nt][2] + b0, acc[mt][nt][3] + b1);
            }
        }
    }
    asm volatile("cp.async.wait_group 0;");
}

// ---------------- elu + LN + fused e2 logits (single-pass stats) -------------
__global__ void __launch_bounds__(256) elu_ln_e2(
    const __half* __restrict__ in, const float* __restrict__ gamma,
    const float* __restrict__ beta, const float* __restrict__ P2,
    __half* __restrict__ out, float* __restrict__ e2)
{
    __shared__ float2 red[8];
    __shared__ float s_mu, s_w;
    int n = blockIdx.x;
    int tid = threadIdx.x;
    const __half* row = in + (size_t)n * FDIM;
    float y[3];
    float s = 0.f, q = 0.f;
#pragma unroll
    for (int i = 0; i < 3; i++) {
        float v = __half2float(row[tid + i * 256]);
        y[i] = v > 0.f ? v : expm1f(v);
        s += y[i];
        q += y[i] * y[i];
    }
    float2 t = block_reduce2_256(s, q, red);
    if (tid == 0) {
        float mu = t.x * (1.f / FDIM);
        s_mu = mu;
        s_w = rsqrtf(t.y * (1.f / FDIM) - mu * mu + 1e-5f);
    }
    __syncthreads();
    float mu = s_mu, w = s_w;
    float o3[3];
    float s0 = 0.f, s1 = 0.f;
#pragma unroll
    for (int i = 0; i < 3; i++) {
        int d = tid + i * 256;
        o3[i] = (y[i] - mu) * w * gamma[d] + beta[d];
        out[(size_t)n * FDIM + d] = __float2half(o3[i]);
        s0 += o3[i] * P2[d * 2 + 0];
        s1 += o3[i] * P2[d * 2 + 1];
    }
    __syncthreads();
    float2 t2 = block_reduce2_256(s0, s1, red);
    if (tid == 0) {
        e2[(size_t)n * 2 + 0] = t2.x;
        e2[(size_t)n * 2 + 1] = t2.y;
    }
}

// ---------------- fused layer-2 epilogue (single-pass stats) -----------------
__global__ void __launch_bounds__(384) agg2_ln_f(
    const __half* __restrict__ pre, const float* __restrict__ e2,
    const void* __restrict__ edge, const float* __restrict__ b2,
    const float* __restrict__ gamma, const float* __restrict__ beta,
    float* __restrict__ out)
{
    __shared__ int    s_src[5];
    __shared__ float  s_alpha[5];
    __shared__ float2 red[12];
    __shared__ float  s_mu, s_w;
    int n = blockIdx.x;
    int tid = threadIdx.x;
    if (tid < 5) {
        int sv = n;
        if (tid < 4) {
            sv = g_is64 ? (int)((const long long*)edge)[(size_t)DEG * n + tid]
                        : ((const int*)edge)[DEG * n + tid];
        }
        s_src[tid] = sv;
    }
    __syncthreads();
    if (tid == 0) {
        float ed = e2[(size_t)n * 2 + 1];
        float l[5];
#pragma unroll
        for (int k = 0; k < 5; k++) {
            float v = e2[(size_t)s_src[k] * 2 + 0] + ed;
            l[k] = v >= 0.f ? v : 0.2f * v;
        }
        float m = l[0];
#pragma unroll
        for (int k = 1; k < 5; k++) m = fmaxf(m, l[k]);
        float s = 0.f;
#pragma unroll
        for (int k = 0; k < 5; k++) { l[k] = expf(l[k] - m); s += l[k]; }
        float inv = 1.f / (s + 1e-16f);
#pragma unroll
        for (int k = 0; k < 5; k++) s_alpha[k] = l[k] * inv;
    }
    __syncthreads();
    int d2 = tid;
    float ax = 0.f, ay = 0.f;
#pragma unroll
    for (int k = 0; k < 5; k++) {
        float2 v = __half22float2(((const __half2*)(pre + (size_t)s_src[k] * FDIM))[d2]);
        float al = s_alpha[k];
        ax += al * v.x;
        ay += al * v.y;
    }
    ax += b2[d2 * 2 + 0];
    ay += b2[d2 * 2 + 1];
    float yx = ax > 0.f ? ax : expm1f(ax);
    float yy = ay > 0.f ? ay : expm1f(ay);
    float2 t = block_reduce2_384(yx + yy, yx * yx + yy * yy, red);
    if (tid == 0) {
        float mu = t.x * (1.f / FDIM);
        s_mu = mu;
        s_w = rsqrtf(t.y * (1.f / FDIM) - mu * mu + 1e-5f);
    }
    __syncthreads();
    float mu = s_mu, w = s_w;
    float ox = (yx - mu) * w * gamma[d2 * 2 + 0] + beta[d2 * 2 + 0];
    float oy = (yy - mu) * w * gamma[d2 * 2 + 1] + beta[d2 * 2 + 1];
    ox = fminf(fmaxf(ox, -10000.f), 10000.f);
    oy = fminf(fmaxf(oy, -10000.f), 10000.f);
    ((float2*)(out + (size_t)n * FDIM))[d2] = make_float2(ox, oy);
}

// ---------------- launch ------------------------------------------------------
extern "C" void kernel_launch(void* const* d_in, const int* in_sizes, int n_in,
                              void* d_out, int out_size)
{
    const float* x   = (const float*)d_in[0];
    const void*  ei  = d_in[1];
    const float* W1  = (const float*)d_in[2];
    const float* a1s = (const float*)d_in[3];
    const float* a1d = (const float*)d_in[4];
    const float* b1  = (const float*)d_in[5];
    const float* W2  = (const float*)d_in[6];
    const float* a2s = (const float*)d_in[7];
    const float* a2d = (const float*)d_in[8];
    const float* b2  = (const float*)d_in[9];
    const float* gm  = (const float*)d_in[10];
    const float* bt  = (const float*)d_in[11];
    float* out = (float*)d_out;

    float *p1, *p2, *e1, *e2, *zb;
    __half *w1ph, *w2rh, *xh, *agg1h, *preh, *x1h;
    cudaGetSymbolAddress((void**)&p1,    g_P1);
    cudaGetSymbolAddress((void**)&p2,    g_P2);
    cudaGetSymbolAddress((void**)&zb,    g_zerob);
    cudaGetSymbolAddress((void**)&w1ph,  g_W1ph);
    cudaGetSymbolAddress((void**)&w2rh,  g_W2rh);
    cudaGetSymbolAddress((void**)&e1,    g_e1);
    cudaGetSymbolAddress((void**)&e2,    g_e2);
    cudaGetSymbolAddress((void**)&xh,    g_xh);
    cudaGetSymbolAddress((void**)&agg1h, g_agg1h);
    cudaGetSymbolAddress((void**)&preh,  g_preh);
    cudaGetSymbolAddress((void**)&x1h,   g_x1h);

    cudaFuncSetAttribute(gemm_fp16, cudaFuncAttributeMaxDynamicSharedMemorySize, GEMM_SMEM);
    cudaFuncSetAttribute(gemm_fp16, cudaFuncAttributePreferredSharedMemoryCarveout, 100);

    const int T = (NNODES / BM) * (FDIM / BN);   // 768 tiles

    prep<<<PREP_GRID, 256>>>(W1, a1s, a1d, W2, a2s, a2d,                      // 1
                             (const unsigned long long*)ei);

    // layer 1 (aggregate-then-project; head-mean folded into W1p)
    compute_e8<<<1024, 256>>>(x, p1, e1, xh);                                 // 2
    aggregate1<<<NNODES / 8, 384>>>(xh, e1, ei, agg1h);                       // 3
    gemm_fp16<<<296, 256, GEMM_SMEM>>>(agg1h, w1ph, b1, preh,                 // 4 (ncu)
                                       FDIM, 4 * FDIM, FDIM / BN, T);
    elu_ln_e2<<<NNODES, 256>>>(preh, gm, bt, p2, x1h, e2);                    // 5

    // layer 2 (project-then-aggregate; bias folded into fused epilogue)
    gemm_fp16<<<296, 256, GEMM_SMEM>>>(x1h, w2rh, zb, preh,                   // 6
                                       FDIM, FDIM, FDIM / BN, T);
    agg2_ln_f<<<NNODES, 384>>>(preh, e2, ei, b2, gm, bt, out);                // 7
}

// round 17
// speedup vs baseline: 1.1209x; 1.0426x over previous
#include <cuda_runtime.h>
#include <cuda_fp16.h>
#include <cstdint>
#include <cstddef>

#define NNODES 16384
#define FDIM   768
#define DEG    4

// ---------------- scratch (device globals; no allocation allowed) ----------
__device__ float  g_P1[FDIM * 8];
__device__ float  g_P2[FDIM * 2];
__device__ float  g_zerob[FDIM];                      // zero bias (static-zeroed)
__device__ __half g_W1ph[(size_t)4 * FDIM * FDIM];    // [3072,768] B GEMM1 (x0.25, fp16)
__device__ __half g_W2rh[(size_t)FDIM * FDIM];        // [768,768]  B GEMM2 (fp16)
__device__ float  g_e1[(size_t)NNODES * 8];
__device__ float  g_e2[(size_t)NNODES * 2];
__device__ __half g_xh[(size_t)NNODES * FDIM];        // x in fp16 (emitted by compute_e8)
__device__ __half g_agg1h[(size_t)NNODES * 4 * FDIM]; // [N,3072] A GEMM1 (fp16)
__device__ __half g_preh[(size_t)NNODES * FDIM];      // GEMM output (fp16)
__device__ __half g_x1h[(size_t)NNODES * FDIM];       // layer-1 output (fp16)
__device__ int    g_is64;

// ---------------- helpers ---------------------------------------------------
__device__ __forceinline__ uint32_t smem_u32(const void* p) {
    uint32_t a;
    asm("{ .reg .u64 t; cvta.to.shared.u64 t, %1; cvt.u32.u64 %0, t; }" : "=r"(a) : "l"(p));
    return a;
}

__device__ __forceinline__ void cp16(uint32_t s, const void* g) {
    asm volatile("cp.async.cg.shared.global [%0], [%1], 16;" :: "r"(s), "l"(g));
}

__device__ __forceinline__ void ldsm_x4(uint32_t* r, uint32_t addr) {
    asm volatile("ldmatrix.sync.aligned.m8n8.x4.shared.b16 {%0,%1,%2,%3}, [%4];"
                 : "=r"(r[0]), "=r"(r[1]), "=r"(r[2]), "=r"(r[3]) : "r"(addr));
}

__device__ __forceinline__ void ldsm_x4_t(uint32_t* r, uint32_t addr) {
    asm volatile("ldmatrix.sync.aligned.m8n8.x4.trans.shared.b16 {%0,%1,%2,%3}, [%4];"
                 : "=r"(r[0]), "=r"(r[1]), "=r"(r[2]), "=r"(r[3]) : "r"(addr));
}

__device__ __forceinline__ void mma_f16(float* d, const uint32_t* a, const uint32_t* b) {
    asm volatile(
        "mma.sync.aligned.m16n8k16.row.col.f32.f16.f16.f32 "
        "{%0,%1,%2,%3}, {%4,%5,%6,%7}, {%8,%9}, {%0,%1,%2,%3};"
        : "+f"(d[0]), "+f"(d[1]), "+f"(d[2]), "+f"(d[3])
        : "r"(a[0]), "r"(a[1]), "r"(a[2]), "r"(a[3]), "r"(b[0]), "r"(b[1]));
}

// quad-value block reduction, 256 threads (8 warps); valid in thread 0
__device__ __forceinline__ float4 block_reduce4_256(float4 v, float4* red) {
#pragma unroll
    for (int o = 16; o; o >>= 1) {
        v.x += __shfl_down_sync(0xffffffffu, v.x, o);
        v.y += __shfl_down_sync(0xffffffffu, v.y, o);
        v.z += __shfl_down_sync(0xffffffffu, v.z, o);
        v.w += __shfl_down_sync(0xffffffffu, v.w, o);
    }
    if ((threadIdx.x & 31) == 0) red[threadIdx.x >> 5] = v;
    __syncthreads();
    float4 r = make_float4(0.f, 0.f, 0.f, 0.f);
    if (threadIdx.x < 8) r = red[threadIdx.x];
    if (threadIdx.x < 32) {
#pragma unroll
        for (int o = 4; o; o >>= 1) {
            r.x += __shfl_down_sync(0xffu, r.x, o);
            r.y += __shfl_down_sync(0xffu, r.y, o);
            r.z += __shfl_down_sync(0xffu, r.z, o);
            r.w += __shfl_down_sync(0xffu, r.w, o);
        }
    }
    return r;
}

// quad-value block reduction, 384 threads (12 warps); valid in thread 0
__device__ __forceinline__ float4 block_reduce4_384(float4 v, float4* red) {
#pragma unroll
    for (int o = 16; o; o >>= 1) {
        v.x += __shfl_down_sync(0xffffffffu, v.x, o);
        v.y += __shfl_down_sync(0xffffffffu, v.y, o);
        v.z += __shfl_down_sync(0xffffffffu, v.z, o);
        v.w += __shfl_down_sync(0xffffffffu, v.w, o);
    }
    if ((threadIdx.x & 31) == 0) red[threadIdx.x >> 5] = v;
    __syncthreads();
    float4 r = make_float4(0.f, 0.f, 0.f, 0.f);
    if (threadIdx.x < 12) r = red[threadIdx.x];
    if (threadIdx.x < 32) {
#pragma unroll
        for (int o = 8; o; o >>= 1) {
            r.x += __shfl_down_sync(0xffffffffu, r.x, o);
            r.y += __shfl_down_sync(0xffffffffu, r.y, o);
            r.z += __shfl_down_sync(0xffffffffu, r.z, o);
            r.w += __shfl_down_sync(0xffffffffu, r.w, o);
        }
    }
    return r;
}

// ---------------- merged prep: probe + P vectors + W repack ------------------
#define PREP_WELEM ((size_t)5 * FDIM * FDIM)
#define PREP_WBLK ((int)((PREP_WELEM + 255) / 256))
#define PREP_GRID (1 + FDIM + PREP_WBLK)

__global__ void __launch_bounds__(256) prep(
    const float* __restrict__ W1, const float* __restrict__ a1s, const float* __restrict__ a1d,
    const float* __restrict__ W2, const float* __restrict__ a2s, const float* __restrict__ a2d,
    const unsigned long long* __restrict__ edge)
{
    int b = blockIdx.x;
    if (b == 0) {
        __shared__ int bad;
        if (threadIdx.x == 0) bad = 0;
        __syncthreads();
        for (int i = threadIdx.x; i < 1024; i += 256)
            if (edge[i] > 0xFFFFFFFFull) bad = 1;
        __syncthreads();
        if (threadIdx.x == 0) g_is64 = bad ? 0 : 1;
        return;
    }
    if (b <= FDIM) {
        int k = b - 1;
        int wid = threadIdx.x >> 5, lane = threadIdx.x & 31;
        {
            int h = wid & 3;
            const float* w = W1 + (size_t)k * (4 * FDIM) + h * FDIM;
            const float* a = (wid < 4 ? a1s : a1d) + h * FDIM;
            float s = 0.f;
            for (int i = lane; i < FDIM; i += 32) s += w[i] * a[i];
#pragma unroll
            for (int o = 16; o; o >>= 1) s += __shfl_down_sync(0xffffffffu, s, o);
            if (lane == 0) g_P1[k * 8 + wid] = s;
        }
        if (wid < 2) {
            const float* w = W2 + (size_t)k * FDIM;
            const float* a = (wid == 0) ? a2s : a2d;
            float s = 0.f;
            for (int i = lane; i < FDIM; i += 32) s += w[i] * a[i];
#pragma unroll
            for (int o = 16; o; o >>= 1) s += __shfl_down_sync(0xffffffffu, s, o);
            if (lane == 0) g_P2[k * 2 + wid] = s;
        }
        return;
    }
    const size_t S1 = (size_t)4 * FDIM * FDIM;
    size_t idx = (size_t)(b - 1 - FDIM) * 256 + threadIdx.x;
    if (idx < S1) {
        int j = (int)(idx % FDIM);
        int r = (int)(idx / FDIM);     // h*768 + k
        int h = r / FDIM, k = r % FDIM;
        g_W1ph[idx] = __float2half(0.25f * W1[(size_t)k * (4 * FDIM) + h * FDIM + j]);
    } else if (idx < PREP_WELEM) {
        size_t i2 = idx - S1;
        g_W2rh[i2] = __float2half(W2[i2]);
    }
}

// ---------------- e1 = x @ P1, also emit x as fp16 (2 nodes/warp) ------------
__global__ void __launch_bounds__(256) compute_e8(
    const float* __restrict__ x, const float* __restrict__ P,
    float* __restrict__ e, __half* __restrict__ xh)
{
    __shared__ __align__(16) float sP[8 * FDIM];   // transposed [j][k]
    for (int i = threadIdx.x; i < 8 * FDIM; i += 256) {
        int j = i / FDIM, k = i % FDIM;
        sP[j * FDIM + k] = P[k * 8 + j];
    }
    __syncthreads();
    const float4* sP4 = (const float4*)sP;         // [8][192]
    int warp = threadIdx.x >> 5, lane = threadIdx.x & 31;
    int n0 = (blockIdx.x * 8 + warp) * 2;          // grid = 1024 -> 2 nodes/warp
    const float4* xr0 = (const float4*)(x + (size_t)n0 * FDIM);
    const float4* xr1 = (const float4*)(x + (size_t)(n0 + 1) * FDIM);
    uint2* xw0 = (uint2*)(xh + (size_t)n0 * FDIM);
    uint2* xw1 = (uint2*)(xh + (size_t)(n0 + 1) * FDIM);
    float acc0[8], acc1[8];
#pragma unroll
    for (int j = 0; j < 8; j++) { acc0[j] = 0.f; acc1[j] = 0.f; }
#pragma unroll
    for (int it = 0; it < 6; it++) {
        float4 v0 = xr0[lane + it * 32];
        float4 v1 = xr1[lane + it * 32];
        {
            __half2 h0 = __floats2half2_rn(v0.x, v0.y);
            __half2 h1 = __floats2half2_rn(v0.z, v0.w);
            uint2 hw; hw.x = *(uint32_t*)&h0; hw.y = *(uint32_t*)&h1;
            xw0[lane + it * 32] = hw;
        }
        {
            __half2 h0 = __floats2half2_rn(v1.x, v1.y);
            __half2 h1 = __floats2half2_rn(v1.z, v1.w);
            uint2 hw; hw.x = *(uint32_t*)&h0; hw.y = *(uint32_t*)&h1;
            xw1[lane + it * 32] = hw;
        }
#pragma unroll
        for (int j = 0; j < 8; j++) {
            float4 p = sP4[j * 192 + lane + it * 32];   // one LDS feeds 2 nodes
            acc0[j] += v0.x * p.x + v0.y * p.y + v0.z * p.z + v0.w * p.w;
            acc1[j] += v1.x * p.x + v1.y * p.y + v1.z * p.z + v1.w * p.w;
        }
    }
#pragma unroll
    for (int j = 0; j < 8; j++) {
        float s0 = acc0[j], s1 = acc1[j];
#pragma unroll
        for (int o = 16; o; o >>= 1) {
            s0 += __shfl_down_sync(0xffffffffu, s0, o);
            s1 += __shfl_down_sync(0xffffffffu, s1, o);
        }
        if (lane == 0) {
            e[(size_t)n0 * 8 + j] = s0;
            e[(size_t)(n0 + 1) * 8 + j] = s1;
        }
    }
}

// ---------------- layer-1 softmax + weighted gather: 8 nodes/block -----------
__global__ void __launch_bounds__(384) aggregate1(
    const __half* __restrict__ x, const float* __restrict__ e,
    const void* __restrict__ edge, __half* __restrict__ agg)
{
    int n0 = blockIdx.x * 8;
    __shared__ int   s_src[8][5];
    __shared__ float s_alpha[8][4][5];
    int tid = threadIdx.x;
    if (tid < 40) {
        int node = tid / 5, k = tid % 5;
        int n = n0 + node;
        int sv = n;
        if (k < 4) {
            sv = g_is64 ? (int)((const long long*)edge)[(size_t)DEG * n + k]
                        : ((const int*)edge)[DEG * n + k];
        }
        s_src[node][k] = sv;
    }
    __syncthreads();
    if (tid < 32) {
        int node = tid >> 2, h = tid & 3;
        int n = n0 + node;
        float ed = e[(size_t)n * 8 + 4 + h];
        float l[5];
#pragma unroll
        for (int k = 0; k < 5; k++) {
            float v = e[(size_t)s_src[node][k] * 8 + h] + ed;
            l[k] = v >= 0.f ? v : 0.2f * v;
        }
        float m = l[0];
#pragma unroll
        for (int k = 1; k < 5; k++) m = fmaxf(m, l[k]);
        float s = 0.f;
#pragma unroll
        for (int k = 0; k < 5; k++) { l[k] = expf(l[k] - m); s += l[k]; }
        float inv = 1.f / (s + 1e-16f);
#pragma unroll
        for (int k = 0; k < 5; k++) s_alpha[node][h][k] = l[k] * inv;
    }
    __syncthreads();
    int d2 = tid;  // 384 threads x 2 dims = 768
#pragma unroll
    for (int node = 0; node < 8; node++) {
        int n = n0 + node;
        float2 xv[5];
#pragma unroll
        for (int k = 0; k < 5; k++)
            xv[k] = __half22float2(
                ((const __half2*)(x + (size_t)s_src[node][k] * FDIM))[d2]);
#pragma unroll
        for (int h = 0; h < 4; h++) {
            float ax = 0.f, ay = 0.f;
#pragma unroll
            for (int k = 0; k < 5; k++) {
                float al = s_alpha[node][h][k];
                ax += al * xv[k].x;
                ay += al * xv[k].y;
            }
            ((__half2*)(agg + ((size_t)n * 4 + h) * FDIM))[d2] =
                __floats2half2_rn(ax, ay);
        }
    }
}

// ---------------- fp16 mma.sync persistent GEMM (BK=32, 4-stage) -------------
#define BM 128
#define BN 128
#define BK 32
#define ASTRH 40
#define BSTRH 136
#define A_STG (BM * ASTRH)
#define B_STG (BK * BSTRH)
#define NSTAGE 4
#define GEMM_SMEM (NSTAGE * (A_STG + B_STG) * 2)

__global__ void __launch_bounds__(256, 2) gemm_fp16(
    const __half* __restrict__ A, const __half* __restrict__ B,
    const float* __restrict__ bias, __half* __restrict__ C,
    int Nn, int K, int ntiles, int T)
{
    extern __shared__ __half hsm[];
    uint32_t asb = smem_u32(hsm);
    uint32_t bsb = asb + NSTAGE * A_STG * 2;

    int tid = threadIdx.x;
    int lane = tid & 31, wid = tid >> 5;
    int warpM = wid & 1, warpN = wid >> 1;
    int g = lane >> 2, tg = lane & 3;
    int KT = K / BK;

    int ar = tid >> 2, ac8 = (tid & 3) * 8;
    int br = tid >> 4, bc8 = (tid & 15) * 8;

    auto load_stage = [&](int s, int k0, int bm, int bn) {
#pragma unroll
        for (int t = 0; t < 2; t++) {
            int r = ar + t * 64;
            cp16(asb + (uint32_t)(s * A_STG + r * ASTRH + ac8) * 2,
                 A + (size_t)(bm + r) * K + k0 + ac8);
        }
#pragma unroll
        for (int t = 0; t < 2; t++) {
            int r = br + t * 16;
            cp16(bsb + (uint32_t)(s * B_STG + r * BSTRH + bc8) * 2,
                 B + (size_t)(k0 + r) * Nn + bn + bc8);
        }
        asm volatile("cp.async.commit_group;");
    };

    uint32_t a_off = (uint32_t)((warpM * 64 + (lane & 15)) * ASTRH + (lane >> 4) * 8);
    uint32_t b_off = (uint32_t)((lane & 15) * BSTRH + warpN * 32 + (lane >> 4) * 8);

    int t0 = blockIdx.x;
    if (t0 >= T) return;
    {
        int bm = (t0 / ntiles) * BM, bn = (t0 % ntiles) * BN;
        load_stage(0, 0, bm, bn);
        load_stage(1, BK, bm, bn);
        load_stage(2, 2 * BK, bm, bn);
    }

    for (int t = t0; t < T; t += gridDim.x) {
        int bm = (t / ntiles) * BM, bn = (t % ntiles) * BN;
        int tn = t + gridDim.x; if (tn >= T) tn = t;
        int bm2 = (tn / ntiles) * BM, bn2 = (tn % ntiles) * BN;

        float acc[4][4][4];
#pragma unroll
        for (int i = 0; i < 4; i++)
#pragma unroll
            for (int j = 0; j < 4; j++)
#pragma unroll
                for (int r = 0; r < 4; r++) acc[i][j][r] = 0.f;

        for (int kt = 0; kt < KT; kt++) {
            asm volatile("cp.async.wait_group 2;");
            __syncthreads();

            int pf = kt + NSTAGE - 1;
            if (pf < KT) load_stage(pf & 3, pf * BK, bm, bn);
            else         load_stage(pf & 3, (pf - KT) * BK, bm2, bn2);

            int buf = kt & 3;
            uint32_t a_base = asb + (buf * A_STG + a_off) * 2;
            uint32_t b_base = bsb + (buf * B_STG + b_off) * 2;
#pragma unroll
            for (int ks = 0; ks < 2; ks++) {
                uint32_t af[4][4], bf[2][4];
#pragma unroll
                for (int mt = 0; mt < 4; mt++)
                    ldsm_x4(af[mt], a_base + (uint32_t)(mt * 16 * ASTRH + ks * 16) * 2);
#pragma unroll
                for (int np = 0; np < 2; np++)
                    ldsm_x4_t(bf[np], b_base + (uint32_t)(ks * 16 * BSTRH + np * 16) * 2);
#pragma unroll
                for (int mt = 0; mt < 4; mt++)
#pragma unroll
                    for (int np = 0; np < 2; np++) {
                        mma_f16(acc[mt][np * 2 + 0], af[mt], &bf[np][0]);
                        mma_f16(acc[mt][np * 2 + 1], af[mt], &bf[np][2]);
                    }
            }
        }

#pragma unroll
        for (int mt = 0; mt < 4; mt++) {
            int row = bm + warpM * 64 + mt * 16 + g;
#pragma unroll
            for (int nt = 0; nt < 4; nt++) {
                int col = bn + warpN * 32 + nt * 8 + tg * 2;
                float b0 = bias[col], b1 = bias[col + 1];
                *(__half2*)(C + (size_t)row * Nn + col) =
                    __floats2half2_rn(acc[mt][nt][0] + b0, acc[mt][nt][1] + b1);
                *(__half2*)(C + (size_t)(row + 8) * Nn + col) =
                    __floats2half2_rn(acc[mt][nt][2] + b0, acc[mt][nt][3] + b1);
            }
        }
    }
    asm volatile("cp.async.wait_group 0;");
}

// ---------------- elu + LN + fused e2 logits (2 nodes/block) -----------------
__global__ void __launch_bounds__(256) elu_ln_e2(
    const __half* __restrict__ in, const float* __restrict__ gamma,
    const float* __restrict__ beta, const float* __restrict__ P2,
    __half* __restrict__ out, float* __restrict__ e2)
{
    __shared__ float4 red[8];
    __shared__ float s_muA, s_wA, s_muB, s_wB;
    int nA = blockIdx.x * 2, nB = nA + 1;
    int tid = threadIdx.x;
    const __half* rowA = in + (size_t)nA * FDIM;
    const __half* rowB = in + (size_t)nB * FDIM;
    float yA[3], yB[3];
    float sA = 0.f, qA = 0.f, sB = 0.f, qB = 0.f;
#pragma unroll
    for (int i = 0; i < 3; i++) {
        float vA = __half2float(rowA[tid + i * 256]);
        float vB = __half2float(rowB[tid + i * 256]);
        yA[i] = vA > 0.f ? vA : expm1f(vA);
        yB[i] = vB > 0.f ? vB : expm1f(vB);
        sA += yA[i]; qA += yA[i] * yA[i];
        sB += yB[i]; qB += yB[i] * yB[i];
    }
    float4 t = block_reduce4_256(make_float4(sA, qA, sB, qB), red);
    if (tid == 0) {
        float muA = t.x * (1.f / FDIM);
        float muB = t.z * (1.f / FDIM);
        s_muA = muA;
        s_wA = rsqrtf(t.y * (1.f / FDIM) - muA * muA + 1e-5f);
        s_muB = muB;
        s_wB = rsqrtf(t.w * (1.f / FDIM) - muB * muB + 1e-5f);
    }
    __syncthreads();
    float muA = s_muA, wA = s_wA, muB = s_muB, wB = s_wB;
    float s0A = 0.f, s1A = 0.f, s0B = 0.f, s1B = 0.f;
#pragma unroll
    for (int i = 0; i < 3; i++) {
        int d = tid + i * 256;
        float gmd = gamma[d], btd = beta[d];
        float p20 = P2[d * 2 + 0], p21 = P2[d * 2 + 1];
        float oA = (yA[i] - muA) * wA * gmd + btd;
        float oB = (yB[i] - muB) * wB * gmd + btd;
        out[(size_t)nA * FDIM + d] = __float2half(oA);
        out[(size_t)nB * FDIM + d] = __float2half(oB);
        s0A += oA * p20; s1A += oA * p21;
        s0B += oB * p20; s1B += oB * p21;
    }
    __syncthreads();
    float4 t2 = block_reduce4_256(make_float4(s0A, s1A, s0B, s1B), red);
    if (tid == 0) {
        e2[(size_t)nA * 2 + 0] = t2.x;
        e2[(size_t)nA * 2 + 1] = t2.y;
        e2[(size_t)nB * 2 + 0] = t2.z;
        e2[(size_t)nB * 2 + 1] = t2.w;
    }
}

// ---------------- fused layer-2 epilogue (2 nodes/block) ---------------------
__global__ void __launch_bounds__(384) agg2_ln_f(
    const __half* __restrict__ pre, const float* __restrict__ e2,
    const void* __restrict__ edge, const float* __restrict__ b2,
    const float* __restrict__ gamma, const float* __restrict__ beta,
    float* __restrict__ out)
{
    __shared__ int    s_src[2][5];
    __shared__ float  s_alpha[2][5];
    __shared__ float4 red[12];
    __shared__ float  s_muA, s_wA, s_muB, s_wB;
    int nA = blockIdx.x * 2;
    int tid = threadIdx.x;
    if (tid < 2) {
        // each thread does its node's full edge-load + softmax privately
        int n = nA + tid;
        int src[5];
        src[4] = n;
#pragma unroll
        for (int k = 0; k < 4; k++) {
            src[k] = g_is64 ? (int)((const long long*)edge)[(size_t)DEG * n + k]
                            : ((const int*)edge)[DEG * n + k];
        }
        float ed = e2[(size_t)n * 2 + 1];
        float l[5];
#pragma unroll
        for (int k = 0; k < 5; k++) {
            float v = e2[(size_t)src[k] * 2 + 0] + ed;
            l[k] = v >= 0.f ? v : 0.2f * v;
        }
        float m = l[0];
#pragma unroll
        for (int k = 1; k < 5; k++) m = fmaxf(m, l[k]);
        float s = 0.f;
#pragma unroll
        for (int k = 0; k < 5; k++) { l[k] = expf(l[k] - m); s += l[k]; }
        float inv = 1.f / (s + 1e-16f);
#pragma unroll
        for (int k = 0; k < 5; k++) {
            s_src[tid][k] = src[k];
            s_alpha[tid][k] = l[k] * inv;
        }
    }
    __syncthreads();
    int d2 = tid;
    float axA = 0.f, ayA = 0.f, axB = 0.f, ayB = 0.f;
#pragma unroll
    for (int k = 0; k < 5; k++) {
        float2 vA = __half22float2(((const __half2*)(pre + (size_t)s_src[0][k] * FDIM))[d2]);
        float2 vB = __half22float2(((const __half2*)(pre + (size_t)s_src[1][k] * FDIM))[d2]);
        float alA = s_alpha[0][k], alB = s_alpha[1][k];
        axA += alA * vA.x; ayA += alA * vA.y;
        axB += alB * vB.x; ayB += alB * vB.y;
    }
    float b20 = b2[d2 * 2 + 0], b21 = b2[d2 * 2 + 1];
    axA += b20; ayA += b21;
    axB += b20; ayB += b21;
    float yxA = axA > 0.f ? axA : expm1f(axA);
    float yyA = ayA > 0.f ? ayA : expm1f(ayA);
    float yxB = axB > 0.f ? axB : expm1f(axB);
    float yyB = ayB > 0.f ? ayB : expm1f(ayB);
    float4 t = block_reduce4_384(
        make_float4(yxA + yyA, yxA * yxA + yyA * yyA,
                    yxB + yyB, yxB * yxB + yyB * yyB), red);
    if (tid == 0) {
        float muA = t.x * (1.f / FDIM);
        float muB = t.z * (1.f / FDIM);
        s_muA = muA;
        s_wA = rsqrtf(t.y * (1.f / FDIM) - muA * muA + 1e-5f);
        s_muB = muB;
        s_wB = rsqrtf(t.w * (1.f / FDIM) - muB * muB + 1e-5f);
    }
    __syncthreads();
    float muA = s_muA, wA = s_wA, muB = s_muB, wB = s_wB;
    float g0 = gamma[d2 * 2 + 0], g1 = gamma[d2 * 2 + 1];
    float bt0 = beta[d2 * 2 + 0], bt1 = beta[d2 * 2 + 1];
    float oxA = (yxA - muA) * wA * g0 + bt0;
    float oyA = (yyA - muA) * wA * g1 + bt1;
    float oxB = (yxB - muB) * wB * g0 + bt0;
    float oyB = (yyB - muB) * wB * g1 + bt1;
    oxA = fminf(fmaxf(oxA, -10000.f), 10000.f);
    oyA = fminf(fmaxf(oyA, -10000.f), 10000.f);
    oxB = fminf(fmaxf(oxB, -10000.f), 10000.f);
    oyB = fminf(fmaxf(oyB, -10000.f), 10000.f);
    ((float2*)(out + (size_t)nA * FDIM))[d2] = make_float2(oxA, oyA);
    ((float2*)(out + (size_t)(nA + 1) * FDIM))[d2] = make_float2(oxB, oyB);
}

// ---------------- launch ------------------------------------------------------
extern "C" void kernel_launch(void* const* d_in, const int* in_sizes, int n_in,
                              void* d_out, int out_size)
{
    const float* x   = (const float*)d_in[0];
    const void*  ei  = d_in[1];
    const float* W1  = (const float*)d_in[2];
    const float* a1s = (const float*)d_in[3];
    const float* a1d = (const float*)d_in[4];
    const float* b1  = (const float*)d_in[5];
    const float* W2  = (const float*)d_in[6];
    const float* a2s = (const float*)d_in[7];
    const float* a2d = (const float*)d_in[8];
    const float* b2  = (const float*)d_in[9];
    const float* gm  = (const float*)d_in[10];
    const float* bt  = (const float*)d_in[11];
    float* out = (float*)d_out;

    float *p1, *p2, *e1, *e2, *zb;
    __half *w1ph, *w2rh, *xh, *agg1h, *preh, *x1h;
    cudaGetSymbolAddress((void**)&p1,    g_P1);
    cudaGetSymbolAddress((void**)&p2,    g_P2);
    cudaGetSymbolAddress((void**)&zb,    g_zerob);
    cudaGetSymbolAddress((void**)&w1ph,  g_W1ph);
    cudaGetSymbolAddress((void**)&w2rh,  g_W2rh);
    cudaGetSymbolAddress((void**)&e1,    g_e1);
    cudaGetSymbolAddress((void**)&e2,    g_e2);
    cudaGetSymbolAddress((void**)&xh,    g_xh);
    cudaGetSymbolAddress((void**)&agg1h, g_agg1h);
    cudaGetSymbolAddress((void**)&preh,  g_preh);
    cudaGetSymbolAddress((void**)&x1h,   g_x1h);

    cudaFuncSetAttribute(gemm_fp16, cudaFuncAttributeMaxDynamicSharedMemorySize, GEMM_SMEM);
    cudaFuncSetAttribute(gemm_fp16, cudaFuncAttributePreferredSharedMemoryCarveout, 100);

    const int T = (NNODES / BM) * (FDIM / BN);   // 768 tiles

    prep<<<PREP_GRID, 256>>>(W1, a1s, a1d, W2, a2s, a2d,                      // 1
                             (const unsigned long long*)ei);

    // layer 1 (aggregate-then-project; head-mean folded into W1p)
    compute_e8<<<1024, 256>>>(x, p1, e1, xh);                                 // 2
    aggregate1<<<NNODES / 8, 384>>>(xh, e1, ei, agg1h);                       // 3
    gemm_fp16<<<296, 256, GEMM_SMEM>>>(agg1h, w1ph, b1, preh,                 // 4 (ncu)
                                       FDIM, 4 * FDIM, FDIM / BN, T);
    elu_ln_e2<<<NNODES / 2, 256>>>(preh, gm, bt, p2, x1h, e2);                // 5

    // layer 2 (project-then-aggregate; bias folded into fused epilogue)
    gemm_fp16<<<296, 256, GEMM_SMEM>>>(x1h, w2rh, zb, preh,                   // 6
                                       FDIM, FDIM, FDIM / BN, T);
    agg2_ln_f<<<NNODES / 2, 384>>>(preh, e2, ei, b2, gm, bt, out);            // 7
}